// round 1
// baseline (speedup 1.0000x reference)
#include <cuda_runtime.h>
#include <math.h>
#include <float.h>

#define Bq 256
#define Dd 128
#define NxMax 200000
#define Kn 50
#define TAUf 0.1f
#define EPSf 1e-8f

// ---------------- device scratch (static; no allocs) ----------------
__device__ float g_Tq[Bq * Dd];
__device__ float g_tqn[Bq];
__device__ float g_xn[NxMax];
__device__ float g_D[(size_t)Bq * NxMax];          // 204.8 MB distance matrix
__device__ float g_comb[512 * Dd];
__device__ float g_cn[512];
__device__ float g_Dc[512 * 512];
__device__ int   g_post[Bq * Kn];
__device__ float g_gval;
__device__ float g_acc[6];                          // kxx,kyy,kxy,anchor,kl
__device__ unsigned int g_hist[256];
__device__ unsigned int g_prefix;
__device__ unsigned int g_rem;
__device__ float g_med[2];

// ---------------- init ----------------
__global__ void k_init() {
    int t = threadIdx.x;
    if (t < 6) g_acc[t] = 0.f;
}

// ---------------- Tq = q @ W^T + b, row norms, anchor ----------------
__global__ void k_tq(const float* __restrict__ q, const float* __restrict__ W,
                     const float* __restrict__ bb) {
    int i = blockIdx.x, t = threadIdx.x;           // 256 blocks, 128 threads
    __shared__ float qs[Dd];
    qs[t] = q[i * Dd + t];
    __syncthreads();
    const float* wr = W + t * Dd;
    float acc = bb[t];
#pragma unroll 16
    for (int c = 0; c < Dd; c++) acc = fmaf(qs[c], __ldg(&wr[c]), acc);
    g_Tq[i * Dd + t] = acc;
    float d = acc - qs[t];
    __shared__ float r1[Dd], r2[Dd];
    r1[t] = acc * acc; r2[t] = d * d;
    __syncthreads();
    for (int s = Dd / 2; s > 0; s >>= 1) {
        if (t < s) { r1[t] += r1[t + s]; r2[t] += r2[t + s]; }
        __syncthreads();
    }
    if (t == 0) { g_tqn[i] = r1[0]; atomicAdd(&g_acc[3], r2[0]); }
}

// ---------------- X row norms ----------------
__global__ void k_xnorm(const float* __restrict__ X, int N) {
    int warp = threadIdx.x >> 5, lane = threadIdx.x & 31;
    int r = blockIdx.x * 8 + warp;
    if (r >= N) return;
    const float* xr = X + (size_t)r * Dd;
    float s = 0.f;
#pragma unroll
    for (int c = lane; c < Dd; c += 32) { float v = xr[c]; s = fmaf(v, v, s); }
    for (int o = 16; o > 0; o >>= 1) s += __shfl_down_sync(0xffffffffu, s, o);
    if (lane == 0) g_xn[r] = s;
}

// ---------------- comb = [Tq ; X[idx]], norms ----------------
__global__ void k_comb(const float* __restrict__ X, const int* __restrict__ idx) {
    int i = blockIdx.x, t = threadIdx.x;           // 512 blocks, 128 threads
    const float* src = (i < Bq) ? (g_Tq + i * Dd) : (X + (size_t)idx[i - Bq] * Dd);
    float v = src[t];
    g_comb[i * Dd + t] = v;
    __shared__ float r1[Dd];
    r1[t] = v * v;
    __syncthreads();
    for (int s = Dd / 2; s > 0; s >>= 1) {
        if (t < s) r1[t] += r1[t + s];
        __syncthreads();
    }
    if (t == 0) g_cn[i] = r1[0];
}

// ---------------- Dc = sqdist(comb, comb) ----------------
__global__ void k_dc() {
    int i = blockIdx.x, t = threadIdx.x;           // 512 blocks, 256 threads
    __shared__ float ci[Dd];
    if (t < Dd) ci[t] = g_comb[i * Dd + t];
    __syncthreads();
    float ni = g_cn[i];
    for (int j = t; j < 512; j += 256) {
        const float* cj = g_comb + j * Dd;
        float dot = 0.f;
#pragma unroll 16
        for (int c = 0; c < Dd; c++) dot = fmaf(ci[c], cj[c], dot);
        g_Dc[i * 512 + j] = fmaxf(ni + g_cn[j] - 2.f * dot, 0.f);
    }
}

// ---------------- median radix select (8-bit digits, multi-kernel) ----------------
__global__ void k_sel_init(unsigned int rank) {
    if (threadIdx.x == 0) { g_prefix = 0u; g_rem = rank; }
    for (int i = threadIdx.x; i < 256; i += blockDim.x) g_hist[i] = 0u;
}

__global__ void k_hist(int pass) {
    __shared__ unsigned int sh[256];
    for (int i = threadIdx.x; i < 256; i += blockDim.x) sh[i] = 0u;
    __syncthreads();
    unsigned int pref = g_prefix;
    unsigned int hm = (pass == 3) ? 0u : (0xFFFFFFFFu << (8 * (pass + 1)));
    for (int id = blockIdx.x * blockDim.x + threadIdx.x; id < 512 * 512;
         id += gridDim.x * blockDim.x) {
        unsigned int u = __float_as_uint(g_Dc[id]);
        if ((u & hm) == pref) atomicAdd(&sh[(u >> (8 * pass)) & 0xFFu], 1u);
    }
    __syncthreads();
    for (int i = threadIdx.x; i < 256; i += blockDim.x)
        if (sh[i]) atomicAdd(&g_hist[i], sh[i]);
}

__global__ void k_decide(int pass, int which) {
    unsigned int rem = g_rem, cum = 0u;
    int b = 0;
    for (; b < 256; b++) {
        unsigned int c = g_hist[b];
        if (cum + c >= rem) break;
        cum += c;
    }
    g_rem = rem - cum;
    g_prefix |= ((unsigned int)b) << (8 * pass);
    if (pass == 0) g_med[which] = __uint_as_float(g_prefix);
    for (int i = 0; i < 256; i++) g_hist[i] = 0u;
}

__global__ void k_gamma() {
    float med = 0.5f * (g_med[0] + g_med[1]);
    float sig = med * 0.5f;
    if (sig < 1e-6f) sig = 1.0f;
    g_gval = 1.0f / (sig + EPSf);
}

// ---------------- MMD kernel sums ----------------
__global__ void k_mmd() {
    float g = g_gval;
    float sxx = 0.f, syy = 0.f, sxy = 0.f;
    for (int id = blockIdx.x * blockDim.x + threadIdx.x; id < 512 * 512;
         id += gridDim.x * blockDim.x) {
        int i = id >> 9, j = id & 511;
        float e = expf(-g * g_Dc[id]);
        if (i < Bq) { if (j < Bq) sxx += e; else sxy += e; }
        else if (j >= Bq) syy += e;
    }
    __shared__ float s1[256], s2[256], s3[256];
    int t = threadIdx.x;
    s1[t] = sxx; s2[t] = syy; s3[t] = sxy;
    __syncthreads();
    for (int s = 128; s > 0; s >>= 1) {
        if (t < s) { s1[t] += s1[t + s]; s2[t] += s2[t + s]; s3[t] += s3[t + s]; }
        __syncthreads();
    }
    if (t == 0) {
        atomicAdd(&g_acc[0], s1[0]);
        atomicAdd(&g_acc[1], s2[0]);
        atomicAdd(&g_acc[2], s3[0]);
    }
}

// ---------------- big distance GEMM: D = tqn + xn - 2 Tq X^T ----------------
#define BM 128
#define BN 128
#define BKG 16
__global__ void __launch_bounds__(256, 2) k_gemm(const float* __restrict__ X, int N) {
    __shared__ float As[BKG][BM];
    __shared__ float Bs[BKG][BN];
    int m0 = blockIdx.y * BM;
    int n0 = blockIdx.x * BN;
    int tid = threadIdx.x;
    int tr = tid >> 4, tc = tid & 15;
    float acc[8][8];
#pragma unroll
    for (int i = 0; i < 8; i++)
#pragma unroll
        for (int j = 0; j < 8; j++) acc[i][j] = 0.f;

    for (int k0 = 0; k0 < Dd; k0 += BKG) {
#pragma unroll
        for (int s = tid; s < 512; s += 256) {
            int r = s >> 2, c4 = s & 3;
            float4 v = *reinterpret_cast<const float4*>(&g_Tq[(m0 + r) * Dd + k0 + c4 * 4]);
            As[c4 * 4 + 0][r] = v.x; As[c4 * 4 + 1][r] = v.y;
            As[c4 * 4 + 2][r] = v.z; As[c4 * 4 + 3][r] = v.w;
        }
#pragma unroll
        for (int s = tid; s < 512; s += 256) {
            int r = s >> 2, c4 = s & 3;
            int n = n0 + r;
            float4 v = make_float4(0.f, 0.f, 0.f, 0.f);
            if (n < N) v = *reinterpret_cast<const float4*>(&X[(size_t)n * Dd + k0 + c4 * 4]);
            Bs[c4 * 4 + 0][r] = v.x; Bs[c4 * 4 + 1][r] = v.y;
            Bs[c4 * 4 + 2][r] = v.z; Bs[c4 * 4 + 3][r] = v.w;
        }
        __syncthreads();
#pragma unroll
        for (int kk = 0; kk < BKG; kk++) {
            float a[8], bv[8];
#pragma unroll
            for (int i = 0; i < 8; i++) a[i] = As[kk][tr * 8 + i];
#pragma unroll
            for (int j = 0; j < 8; j++) bv[j] = Bs[kk][tc * 8 + j];
#pragma unroll
            for (int i = 0; i < 8; i++)
#pragma unroll
                for (int j = 0; j < 8; j++) acc[i][j] = fmaf(a[i], bv[j], acc[i][j]);
        }
        __syncthreads();
    }
#pragma unroll
    for (int i = 0; i < 8; i++) {
        int m = m0 + tr * 8 + i;
        float tn = g_tqn[m];
#pragma unroll
        for (int j = 0; j < 8; j += 4) {
            int n = n0 + tc * 8 + j;
            if (n + 3 < N) {
                float4 o;
                o.x = fmaxf(tn + g_xn[n + 0] - 2.f * acc[i][j + 0], 0.f);
                o.y = fmaxf(tn + g_xn[n + 1] - 2.f * acc[i][j + 1], 0.f);
                o.z = fmaxf(tn + g_xn[n + 2] - 2.f * acc[i][j + 2], 0.f);
                o.w = fmaxf(tn + g_xn[n + 3] - 2.f * acc[i][j + 3], 0.f);
                *reinterpret_cast<float4*>(&g_D[(size_t)m * N + n]) = o;
            } else {
                for (int e = 0; e < 4; e++)
                    if (n + e < N)
                        g_D[(size_t)m * N + n + e] =
                            fmaxf(tn + g_xn[n + e] - 2.f * acc[i][j + e], 0.f);
            }
        }
    }
}

// ---------------- per-row top-50 via threshold stream + bitonic compaction ----------------
__device__ __forceinline__ void bitonic4096(unsigned long long* a, int tid) {
    for (int k = 2; k <= 4096; k <<= 1) {
        for (int j = k >> 1; j > 0; j >>= 1) {
            for (int i = tid; i < 4096; i += 512) {
                int ixj = i ^ j;
                if (ixj > i) {
                    bool up = ((i & k) == 0);
                    unsigned long long x = a[i], y = a[ixj];
                    if ((x > y) == up) { a[i] = y; a[ixj] = x; }
                }
            }
            __syncthreads();
        }
    }
}

__global__ void __launch_bounds__(512) k_topk(int N) {
    __shared__ unsigned long long cand[4096];
    __shared__ int cnt;
    __shared__ int csnap;
    __shared__ float curT;
    int row = blockIdx.x, tid = threadIdx.x;
    if (tid == 0) { cnt = 0; curT = FLT_MAX; }
    __syncthreads();
    const float* Drow = g_D + (size_t)row * N;
    for (int base = 0; base < N; base += 2048) {
        float T = curT;
#pragma unroll
        for (int s2 = 0; s2 < 4; s2++) {
            int j = base + s2 * 512 + tid;
            if (j < N) {
                float v = __ldg(&Drow[j]);
                if (v < T) {
                    int p = atomicAdd(&cnt, 1);
                    cand[p] = (((unsigned long long)__float_as_uint(v)) << 32) |
                              (unsigned int)j;
                }
            }
        }
        __syncthreads();
        if (tid == 0) csnap = cnt;
        __syncthreads();
        if (csnap > 2048) {
            for (int i = csnap + tid; i < 4096; i += 512) cand[i] = 0xFFFFFFFFFFFFFFFFULL;
            __syncthreads();
            bitonic4096(cand, tid);
            if (tid == 0) {
                cnt = Kn;
                curT = __uint_as_float((unsigned int)(cand[Kn - 1] >> 32));
            }
            __syncthreads();
        }
    }
    if (tid == 0) csnap = cnt;
    __syncthreads();
    for (int i = csnap + tid; i < 4096; i += 512) cand[i] = 0xFFFFFFFFFFFFFFFFULL;
    __syncthreads();
    bitonic4096(cand, tid);
    if (tid < Kn) g_post[row * Kn + tid] = (int)(cand[tid] & 0xFFFFFFFFu);
}

// ---------------- union-KL per row ----------------
__global__ void k_kl(const float* __restrict__ X, const float* __restrict__ pw,
                     const int* __restrict__ pi, const int* __restrict__ qind) {
    int row = blockIdx.x, t = threadIdx.x;         // 256 blocks, 128 threads
    __shared__ float Tqs[Dd];
    __shared__ int cat[2 * Kn];
    __shared__ float prew[Kn], postw[Kn], l2s[Kn];
    __shared__ float pm[2 * Kn], qm[2 * Kn], mlt[2 * Kn];
    __shared__ float red[Dd];
    __shared__ float Sp, Sq;
    Tqs[t] = g_Tq[row * Dd + t];
    int qi = qind[row];
    if (t < Kn) {
        cat[t] = pi[qi * Kn + t];
        prew[t] = pw[qi * Kn + t];
        cat[Kn + t] = g_post[row * Kn + t];
    }
    __syncthreads();
    int warp = t >> 5, lane = t & 31;
    for (int k = warp; k < Kn; k += 4) {
        const float* xr = X + (size_t)cat[Kn + k] * Dd;
        float s = 0.f;
#pragma unroll
        for (int c = lane; c < Dd; c += 32) {
            float d = Tqs[c] - xr[c];
            s = fmaf(d, d, s);
        }
        for (int o = 16; o > 0; o >>= 1) s += __shfl_down_sync(0xffffffffu, s, o);
        if (lane == 0) l2s[k] = s;
    }
    __syncthreads();
    if (t == 0) {
        float mx = -FLT_MAX;
        for (int k = 0; k < Kn; k++) {
            float z = -l2s[k] * (1.f / TAUf);
            if (z > mx) mx = z;
        }
        float sm = 0.f;
        for (int k = 0; k < Kn; k++) {
            float e = expf(-l2s[k] * (1.f / TAUf) - mx);
            postw[k] = e; sm += e;
        }
        float inv = 1.f / sm;
        for (int k = 0; k < Kn; k++) postw[k] *= inv;
    }
    __syncthreads();
    if (t < 2 * Kn) {
        int id = cat[t];
        int m = 0; float pr = 0.f, qr = 0.f;
        for (int k = 0; k < 2 * Kn; k++) m += (cat[k] == id);
        for (int k = 0; k < Kn; k++) {
            if (cat[k] == id) pr += prew[k];
            if (cat[Kn + k] == id) qr += postw[k];
        }
        pm[t] = fmaxf(pr, EPSf); qm[t] = fmaxf(qr, EPSf); mlt[t] = (float)m;
    }
    __syncthreads();
    if (t == 0) {
        float a = 0.f, bs = 0.f;
        for (int m2 = 0; m2 < 2 * Kn; m2++) { a += pm[m2] / mlt[m2]; bs += qm[m2] / mlt[m2]; }
        Sp = a; Sq = bs;
    }
    __syncthreads();
    float klc = 0.f;
    if (t < 2 * Kn) {
        float p = pm[t] / Sp, q2 = qm[t] / Sq;
        klc = p * (logf(p) - logf(q2)) / mlt[t];
    }
    red[t] = klc;
    __syncthreads();
    for (int s = Dd / 2; s > 0; s >>= 1) {
        if (t < s) red[t] += red[t + s];
        __syncthreads();
    }
    if (t == 0) atomicAdd(&g_acc[4], red[0]);
}

// ---------------- finalize ----------------
__global__ void k_final(const float* __restrict__ W, const float* __restrict__ b,
                        float* __restrict__ out) {
    __shared__ float red[256];
    int t = threadIdx.x;
    float s = 0.f;
    for (int i = t; i < Dd * Dd; i += 256) { float w = W[i]; s = fmaf(w, w, s); }
    if (t < Dd) { float bv = b[t]; s = fmaf(bv, bv, s); }
    red[t] = s;
    __syncthreads();
    for (int st = 128; st > 0; st >>= 1) {
        if (t < st) red[t] += red[t + st];
        __syncthreads();
    }
    if (t == 0) {
        float reg = 0.5f * red[0];
        float inv = 1.0f / 65536.0f;
        float kxx = g_acc[0] * inv, kyy = g_acc[1] * inv, kxy = g_acc[2] * inv;
        float dist = fmaxf(kxx + kyy - 2.f * kxy, 0.f);
        float knn = g_acc[4] / 256.0f;
        float anchor = g_acc[3] / 256.0f;
        float total = dist + knn + 1e-4f * reg + anchor;
        out[0] = total; out[1] = dist; out[2] = knn; out[3] = anchor;
    }
}

// ---------------- launch ----------------
extern "C" void kernel_launch(void* const* d_in, const int* in_sizes, int n_in,
                              void* d_out, int out_size) {
    const float* q  = (const float*)d_in[0];
    const float* X  = (const float*)d_in[1];
    const float* W  = (const float*)d_in[2];
    const float* b  = (const float*)d_in[3];
    const float* pw = (const float*)d_in[4];
    const int* pi   = (const int*)d_in[5];
    const int* qi   = (const int*)d_in[6];
    const int* idx  = (const int*)d_in[7];
    int N = in_sizes[1] / Dd;                       // 200000
    if (N > NxMax) N = NxMax;

    k_init<<<1, 32>>>();
    k_tq<<<Bq, Dd>>>(q, W, b);
    k_xnorm<<<(N + 7) / 8, 256>>>(X, N);
    k_comb<<<512, Dd>>>(X, idx);
    k_dc<<<512, 256>>>();
    // exact median of 512x512 = avg of ranks 131072, 131073 (1-based)
    for (int r = 0; r < 2; r++) {
        k_sel_init<<<1, 256>>>((unsigned int)(131072 + r));
        for (int p = 3; p >= 0; p--) {
            k_hist<<<256, 256>>>(p);
            k_decide<<<1, 1>>>(p, r);
        }
    }
    k_gamma<<<1, 1>>>();
    k_mmd<<<512, 256>>>();
    dim3 gg((N + BN - 1) / BN, Bq / BM);
    k_gemm<<<gg, 256>>>(X, N);
    k_topk<<<Bq, 512>>>(N);
    k_kl<<<Bq, Dd>>>(X, pw, pi, qi);
    k_final<<<1, 256>>>(W, b, (float*)d_out);
}

// round 2
// speedup vs baseline: 1.7171x; 1.7171x over previous
#include <cuda_runtime.h>
#include <cuda_bf16.h>
#include <math.h>
#include <float.h>

#define Bq 256
#define Dd 128
#define NxMax 200000
#define Kn 50
#define TAUf 0.1f
#define EPSf 1e-8f

// ---------------- device scratch (static; no allocs) ----------------
__device__ float g_Tq[Bq * Dd];
__device__ __nv_bfloat16 g_Tqb[Bq * Dd];
__device__ float g_tqn[Bq];
__device__ float g_xn[NxMax];
__device__ __nv_bfloat16 g_Xb[(size_t)NxMax * Dd];       // 51.2 MB bf16 X
__device__ __nv_bfloat16 g_Db[(size_t)Bq * NxMax];       // 102.4 MB bf16 distances
__device__ float g_comb[512 * Dd];
__device__ float g_cn[512];
__device__ float g_Dc[512 * 512];
__device__ int   g_post[Bq * Kn];
__device__ float g_gval;
__device__ float g_acc[6];                               // kxx,kyy,kxy,anchor,kl
__device__ unsigned int g_hist[256];
__device__ unsigned int g_prefix;
__device__ unsigned int g_rem;
__device__ float g_med[2];
__device__ unsigned int g_cntle;
__device__ unsigned int g_minab;

// ---------------- X -> bf16 + row norms + zero accumulators ----------------
__global__ void k_convX(const float* __restrict__ X, int N) {
    int warp = threadIdx.x >> 5, lane = threadIdx.x & 31;
    if (blockIdx.x == 0 && threadIdx.x < 6) g_acc[threadIdx.x] = 0.f;
    int r = blockIdx.x * 8 + warp;
    if (r >= N) return;
    float4 v = *reinterpret_cast<const float4*>(X + (size_t)r * Dd + lane * 4);
    float s = v.x * v.x + v.y * v.y + v.z * v.z + v.w * v.w;
    __nv_bfloat162 h0 = __floats2bfloat162_rn(v.x, v.y);
    __nv_bfloat162 h1 = __floats2bfloat162_rn(v.z, v.w);
    uint2 packed;
    packed.x = *reinterpret_cast<unsigned*>(&h0);
    packed.y = *reinterpret_cast<unsigned*>(&h1);
    *reinterpret_cast<uint2*>(&g_Xb[(size_t)r * Dd + lane * 4]) = packed;
    for (int o = 16; o > 0; o >>= 1) s += __shfl_down_sync(0xffffffffu, s, o);
    if (lane == 0) g_xn[r] = s;
}

// ---------------- Tq = q @ W^T + b (fp32 + bf16), row norms, anchor ----------------
__global__ void k_tq(const float* __restrict__ q, const float* __restrict__ W,
                     const float* __restrict__ bb) {
    int i = blockIdx.x, t = threadIdx.x;           // 256 blocks, 128 threads
    __shared__ float qs[Dd];
    qs[t] = q[i * Dd + t];
    __syncthreads();
    const float* wr = W + t * Dd;
    float acc = bb[t];
#pragma unroll 16
    for (int c = 0; c < Dd; c++) acc = fmaf(qs[c], __ldg(&wr[c]), acc);
    g_Tq[i * Dd + t] = acc;
    g_Tqb[i * Dd + t] = __float2bfloat16(acc);
    float d = acc - qs[t];
    __shared__ float r1[Dd], r2[Dd];
    r1[t] = acc * acc; r2[t] = d * d;
    __syncthreads();
    for (int s = Dd / 2; s > 0; s >>= 1) {
        if (t < s) { r1[t] += r1[t + s]; r2[t] += r2[t + s]; }
        __syncthreads();
    }
    if (t == 0) { g_tqn[i] = r1[0]; atomicAdd(&g_acc[3], r2[0]); }
}

// ---------------- comb = [Tq ; X[idx]], norms ----------------
__global__ void k_comb(const float* __restrict__ X, const int* __restrict__ idx) {
    int i = blockIdx.x, t = threadIdx.x;           // 512 blocks, 128 threads
    const float* src = (i < Bq) ? (g_Tq + i * Dd) : (X + (size_t)idx[i - Bq] * Dd);
    float v = src[t];
    g_comb[i * Dd + t] = v;
    __shared__ float r1[Dd];
    r1[t] = v * v;
    __syncthreads();
    for (int s = Dd / 2; s > 0; s >>= 1) {
        if (t < s) r1[t] += r1[t + s];
        __syncthreads();
    }
    if (t == 0) g_cn[i] = r1[0];
}

// ---------------- Dc = sqdist(comb, comb); init select state in block 0 ----------------
__global__ void k_dc() {
    int i = blockIdx.x, t = threadIdx.x;           // 512 blocks, 256 threads
    if (i == 0) {
        g_hist[t] = 0u;
        if (t == 0) {
            g_prefix = 0u; g_rem = 131072u;        // rank of lower median (1-based)
            g_cntle = 0u; g_minab = 0x7f7fffffu;   // FLT_MAX bits
        }
    }
    __shared__ float ci[Dd];
    if (t < Dd) ci[t] = g_comb[i * Dd + t];
    __syncthreads();
    float ni = g_cn[i];
    for (int j = t; j < 512; j += 256) {
        const float* cj = g_comb + j * Dd;
        float dot = 0.f;
#pragma unroll 16
        for (int c = 0; c < Dd; c++) dot = fmaf(ci[c], cj[c], dot);
        g_Dc[i * 512 + j] = fmaxf(ni + g_cn[j] - 2.f * dot, 0.f);
    }
}

// ---------------- median radix select: histogram pass ----------------
__global__ void k_hist(int pass) {
    __shared__ unsigned int sh[256];
    for (int i = threadIdx.x; i < 256; i += blockDim.x) sh[i] = 0u;
    __syncthreads();
    unsigned int pref = g_prefix;
    unsigned int hm = (pass == 3) ? 0u : (0xFFFFFFFFu << (8 * (pass + 1)));
    for (int id = blockIdx.x * blockDim.x + threadIdx.x; id < 512 * 512;
         id += gridDim.x * blockDim.x) {
        unsigned int u = __float_as_uint(g_Dc[id]);
        if ((u & hm) == pref) atomicAdd(&sh[(u >> (8 * pass)) & 0xFFu], 1u);
    }
    __syncthreads();
    for (int i = threadIdx.x; i < 256; i += blockDim.x)
        if (sh[i]) atomicAdd(&g_hist[i], sh[i]);
}

// ---------------- parallel decide: scan 256 bins, pick bucket, reset hist ----------------
__global__ void k_decide(int pass) {
    __shared__ unsigned int s[256];
    int t = threadIdx.x;
    unsigned int c = g_hist[t];
    g_hist[t] = 0u;                                 // reset for next pass
    s[t] = c;
    __syncthreads();
    for (int off = 1; off < 256; off <<= 1) {
        unsigned int v = (t >= off) ? s[t - off] : 0u;
        __syncthreads();
        s[t] += v;
        __syncthreads();
    }
    unsigned int rem = g_rem;
    unsigned int cum = s[t];
    unsigned int prev = (t > 0) ? s[t - 1] : 0u;
    if (cum >= rem && prev < rem) {
        g_rem = rem - prev;
        unsigned int np = g_prefix | ((unsigned int)t << (8 * pass));
        g_prefix = np;
        if (pass == 0) g_med[0] = __uint_as_float(np);
    }
}

// ---------------- count <= v1, min above v1 ----------------
__global__ void k_cntmin() {
    float v1 = g_med[0];
    unsigned int c = 0;
    float mn = FLT_MAX;
    for (int id = blockIdx.x * blockDim.x + threadIdx.x; id < 512 * 512;
         id += gridDim.x * blockDim.x) {
        float v = g_Dc[id];
        if (v <= v1) c++;
        else mn = fminf(mn, v);
    }
    __shared__ unsigned int sc[256];
    __shared__ unsigned int sm[256];
    int t = threadIdx.x;
    sc[t] = c; sm[t] = __float_as_uint(mn);
    __syncthreads();
    for (int s = 128; s > 0; s >>= 1) {
        if (t < s) { sc[t] += sc[t + s]; sm[t] = min(sm[t], sm[t + s]); }
        __syncthreads();
    }
    if (t == 0) {
        atomicAdd(&g_cntle, sc[0]);
        atomicMin(&g_minab, sm[0]);
    }
}

__global__ void k_gamma() {
    float v1 = g_med[0];
    float v2 = (g_cntle >= 131073u) ? v1 : __uint_as_float(g_minab);
    float med = 0.5f * (v1 + v2);
    float sig = med * 0.5f;
    if (sig < 1e-6f) sig = 1.0f;
    g_gval = 1.0f / (sig + EPSf);
}

// ---------------- MMD kernel sums ----------------
__global__ void k_mmd() {
    float g = g_gval;
    float sxx = 0.f, syy = 0.f, sxy = 0.f;
    for (int id = blockIdx.x * blockDim.x + threadIdx.x; id < 512 * 512;
         id += gridDim.x * blockDim.x) {
        int i = id >> 9, j = id & 511;
        float e = expf(-g * g_Dc[id]);
        if (i < Bq) { if (j < Bq) sxx += e; else sxy += e; }
        else if (j >= Bq) syy += e;
    }
    __shared__ float s1[256], s2[256], s3[256];
    int t = threadIdx.x;
    s1[t] = sxx; s2[t] = syy; s3[t] = sxy;
    __syncthreads();
    for (int s = 128; s > 0; s >>= 1) {
        if (t < s) { s1[t] += s1[t + s]; s2[t] += s2[t + s]; s3[t] += s3[t + s]; }
        __syncthreads();
    }
    if (t == 0) {
        atomicAdd(&g_acc[0], s1[0]);
        atomicAdd(&g_acc[1], s2[0]);
        atomicAdd(&g_acc[2], s3[0]);
    }
}

// ---------------- bf16 tensor-core distance GEMM ----------------
// D[m][n] = max(tqn[m] + xn[n] - 2 * Tq[m,:] . X[n,:], 0), stored bf16.
// Block tile 128(M) x 128(N), K=128 staged in two 64-chunks.
// 8 warps: 4(M) x 2(N); warp tile 32 x 64 via mma.sync m16n8k16 (2 x 8 frags).
#define GBN 128
#define SSTR 72   // smem row stride in bf16 elems (64 data + 8 pad) -> conflict-free
__global__ void __launch_bounds__(256) k_gemm(int N) {
    __shared__ __align__(16) __nv_bfloat16 As[128 * SSTR];
    __shared__ __align__(16) __nv_bfloat16 Bs[128 * SSTR];
    __shared__ float tns[128], xns[128];
    int m0 = blockIdx.y * 128;
    int n0 = blockIdx.x * GBN;
    int tid = threadIdx.x;
    int warp = tid >> 5, lane = tid & 31;
    int g = lane >> 2, tg = lane & 3;
    int wm = (warp >> 1) * 32;                     // 0,32,64,96
    int wn = (warp & 1) * 64;                      // 0,64
    float acc[2][8][4];
#pragma unroll
    for (int i = 0; i < 2; i++)
#pragma unroll
        for (int j = 0; j < 8; j++)
#pragma unroll
            for (int e = 0; e < 4; e++) acc[i][j][e] = 0.f;

    if (tid < 128) {
        tns[tid] = g_tqn[m0 + tid];
        int n = n0 + tid;
        xns[tid] = (n < N) ? g_xn[n] : 0.f;
    }

#pragma unroll
    for (int kk0 = 0; kk0 < Dd; kk0 += 64) {
        __syncthreads();
        // load A tile: 128 rows x 64 cols bf16, uint4 = 8 bf16
#pragma unroll
        for (int s = tid; s < 1024; s += 256) {
            int r = s >> 3, c = (s & 7) * 8;
            *reinterpret_cast<uint4*>(&As[r * SSTR + c]) =
                *reinterpret_cast<const uint4*>(&g_Tqb[(m0 + r) * Dd + kk0 + c]);
        }
#pragma unroll
        for (int s = tid; s < 1024; s += 256) {
            int r = s >> 3, c = (s & 7) * 8;
            int n = n0 + r;
            uint4 v = make_uint4(0u, 0u, 0u, 0u);
            if (n < N) v = *reinterpret_cast<const uint4*>(&g_Xb[(size_t)n * Dd + kk0 + c]);
            *reinterpret_cast<uint4*>(&Bs[r * SSTR + c]) = v;
        }
        __syncthreads();
#pragma unroll
        for (int ks = 0; ks < 64; ks += 16) {
            unsigned a[2][4], b[8][2];
#pragma unroll
            for (int i = 0; i < 2; i++) {
                int r = wm + i * 16 + g;
                int c = ks + tg * 2;
                a[i][0] = *reinterpret_cast<unsigned*>(&As[r * SSTR + c]);
                a[i][1] = *reinterpret_cast<unsigned*>(&As[(r + 8) * SSTR + c]);
                a[i][2] = *reinterpret_cast<unsigned*>(&As[r * SSTR + c + 8]);
                a[i][3] = *reinterpret_cast<unsigned*>(&As[(r + 8) * SSTR + c + 8]);
            }
#pragma unroll
            for (int j = 0; j < 8; j++) {
                int r = wn + j * 8 + g;
                int c = ks + tg * 2;
                b[j][0] = *reinterpret_cast<unsigned*>(&Bs[r * SSTR + c]);
                b[j][1] = *reinterpret_cast<unsigned*>(&Bs[r * SSTR + c + 8]);
            }
#pragma unroll
            for (int i = 0; i < 2; i++)
#pragma unroll
                for (int j = 0; j < 8; j++)
                    asm volatile(
                        "mma.sync.aligned.m16n8k16.row.col.f32.bf16.bf16.f32 "
                        "{%0,%1,%2,%3}, {%4,%5,%6,%7}, {%8,%9}, {%0,%1,%2,%3};"
                        : "+f"(acc[i][j][0]), "+f"(acc[i][j][1]),
                          "+f"(acc[i][j][2]), "+f"(acc[i][j][3])
                        : "r"(a[i][0]), "r"(a[i][1]), "r"(a[i][2]), "r"(a[i][3]),
                          "r"(b[j][0]), "r"(b[j][1]));
        }
    }

    // epilogue: d2 = tn + xn - 2*dot, clamp, bf16x2 store
#pragma unroll
    for (int i = 0; i < 2; i++) {
        int r0 = wm + i * 16 + g;
        int m = m0 + r0;
        float tn0 = tns[r0], tn1 = tns[r0 + 8];
#pragma unroll
        for (int j = 0; j < 8; j++) {
            int cl = wn + j * 8 + tg * 2;
            int n = n0 + cl;
            if (n < N) {                           // N even, n even -> n+1 < N too
                float xa = xns[cl], xb = xns[cl + 1];
                float d00 = fmaxf(tn0 + xa - 2.f * acc[i][j][0], 0.f);
                float d01 = fmaxf(tn0 + xb - 2.f * acc[i][j][1], 0.f);
                float d10 = fmaxf(tn1 + xa - 2.f * acc[i][j][2], 0.f);
                float d11 = fmaxf(tn1 + xb - 2.f * acc[i][j][3], 0.f);
                __nv_bfloat162 p0 = __floats2bfloat162_rn(d00, d01);
                __nv_bfloat162 p1 = __floats2bfloat162_rn(d10, d11);
                *reinterpret_cast<unsigned*>(&g_Db[(size_t)m * N + n]) =
                    *reinterpret_cast<unsigned*>(&p0);
                *reinterpret_cast<unsigned*>(&g_Db[(size_t)(m + 8) * N + n]) =
                    *reinterpret_cast<unsigned*>(&p1);
            }
        }
    }
}

// ---------------- per-row top-50 via threshold stream + bitonic compaction ----------------
__device__ __forceinline__ void bitonic4096(unsigned long long* a, int tid) {
    for (int k = 2; k <= 4096; k <<= 1) {
        for (int j = k >> 1; j > 0; j >>= 1) {
            for (int i = tid; i < 4096; i += 512) {
                int ixj = i ^ j;
                if (ixj > i) {
                    bool up = ((i & k) == 0);
                    unsigned long long x = a[i], y = a[ixj];
                    if ((x > y) == up) { a[i] = y; a[ixj] = x; }
                }
            }
            __syncthreads();
        }
    }
}

__global__ void __launch_bounds__(512) k_topk(int N) {
    __shared__ unsigned long long cand[4096];
    __shared__ int cnt;
    __shared__ int csnap;
    __shared__ float curT;
    int row = blockIdx.x, tid = threadIdx.x;
    if (tid == 0) { cnt = 0; curT = FLT_MAX; }
    __syncthreads();
    const __nv_bfloat16* Drow = g_Db + (size_t)row * N;
    for (int base = 0; base < N; base += 2048) {
        float T = curT;
        int j0 = base + tid * 4;                   // 4 consecutive bf16 per thread
        if (j0 < N) {                              // N % 4 == 0 -> j0+3 < N
            uint2 u = *reinterpret_cast<const uint2*>(&Drow[j0]);
            unsigned h[4] = { u.x & 0xFFFFu, u.x >> 16, u.y & 0xFFFFu, u.y >> 16 };
#pragma unroll
            for (int e = 0; e < 4; e++) {
                float v = __uint_as_float(h[e] << 16);
                if (v < T) {
                    int p = atomicAdd(&cnt, 1);
                    cand[p] = (((unsigned long long)__float_as_uint(v)) << 32) |
                              (unsigned int)(j0 + e);
                }
            }
        }
        __syncthreads();
        if (tid == 0) csnap = cnt;
        __syncthreads();
        if (csnap > 2048) {
            for (int i = csnap + tid; i < 4096; i += 512) cand[i] = 0xFFFFFFFFFFFFFFFFULL;
            __syncthreads();
            bitonic4096(cand, tid);
            if (tid == 0) {
                cnt = Kn;
                curT = __uint_as_float((unsigned int)(cand[Kn - 1] >> 32));
            }
            __syncthreads();
        }
    }
    if (tid == 0) csnap = cnt;
    __syncthreads();
    for (int i = csnap + tid; i < 4096; i += 512) cand[i] = 0xFFFFFFFFFFFFFFFFULL;
    __syncthreads();
    bitonic4096(cand, tid);
    if (tid < Kn) g_post[row * Kn + tid] = (int)(cand[tid] & 0xFFFFFFFFu);
}

// ---------------- union-KL per row (exact fp32) ----------------
__global__ void k_kl(const float* __restrict__ X, const float* __restrict__ pw,
                     const int* __restrict__ pi, const int* __restrict__ qind) {
    int row = blockIdx.x, t = threadIdx.x;         // 256 blocks, 128 threads
    __shared__ float Tqs[Dd];
    __shared__ int cat[2 * Kn];
    __shared__ float prew[Kn], postw[Kn], l2s[Kn];
    __shared__ float pm[2 * Kn], qm[2 * Kn], mlt[2 * Kn];
    __shared__ float red[Dd];
    __shared__ float Sp, Sq;
    Tqs[t] = g_Tq[row * Dd + t];
    int qi = qind[row];
    if (t < Kn) {
        cat[t] = pi[qi * Kn + t];
        prew[t] = pw[qi * Kn + t];
        cat[Kn + t] = g_post[row * Kn + t];
    }
    __syncthreads();
    int warp = t >> 5, lane = t & 31;
    for (int k = warp; k < Kn; k += 4) {
        const float* xr = X + (size_t)cat[Kn + k] * Dd;
        float s = 0.f;
#pragma unroll
        for (int c = lane; c < Dd; c += 32) {
            float d = Tqs[c] - xr[c];
            s = fmaf(d, d, s);
        }
        for (int o = 16; o > 0; o >>= 1) s += __shfl_down_sync(0xffffffffu, s, o);
        if (lane == 0) l2s[k] = s;
    }
    __syncthreads();
    if (t == 0) {
        float mx = -FLT_MAX;
        for (int k = 0; k < Kn; k++) {
            float z = -l2s[k] * (1.f / TAUf);
            if (z > mx) mx = z;
        }
        float sm = 0.f;
        for (int k = 0; k < Kn; k++) {
            float e = expf(-l2s[k] * (1.f / TAUf) - mx);
            postw[k] = e; sm += e;
        }
        float inv = 1.f / sm;
        for (int k = 0; k < Kn; k++) postw[k] *= inv;
    }
    __syncthreads();
    if (t < 2 * Kn) {
        int id = cat[t];
        int m = 0; float pr = 0.f, qr = 0.f;
        for (int k = 0; k < 2 * Kn; k++) m += (cat[k] == id);
        for (int k = 0; k < Kn; k++) {
            if (cat[k] == id) pr += prew[k];
            if (cat[Kn + k] == id) qr += postw[k];
        }
        pm[t] = fmaxf(pr, EPSf); qm[t] = fmaxf(qr, EPSf); mlt[t] = (float)m;
    }
    __syncthreads();
    if (t == 0) {
        float a = 0.f, bs = 0.f;
        for (int m2 = 0; m2 < 2 * Kn; m2++) { a += pm[m2] / mlt[m2]; bs += qm[m2] / mlt[m2]; }
        Sp = a; Sq = bs;
    }
    __syncthreads();
    float klc = 0.f;
    if (t < 2 * Kn) {
        float p = pm[t] / Sp, q2 = qm[t] / Sq;
        klc = p * (logf(p) - logf(q2)) / mlt[t];
    }
    red[t] = klc;
    __syncthreads();
    for (int s = Dd / 2; s > 0; s >>= 1) {
        if (t < s) red[t] += red[t + s];
        __syncthreads();
    }
    if (t == 0) atomicAdd(&g_acc[4], red[0]);
}

// ---------------- finalize ----------------
__global__ void k_final(const float* __restrict__ W, const float* __restrict__ b,
                        float* __restrict__ out) {
    __shared__ float red[256];
    int t = threadIdx.x;
    float s = 0.f;
    for (int i = t; i < Dd * Dd; i += 256) { float w = W[i]; s = fmaf(w, w, s); }
    if (t < Dd) { float bv = b[t]; s = fmaf(bv, bv, s); }
    red[t] = s;
    __syncthreads();
    for (int st = 128; st > 0; st >>= 1) {
        if (t < st) red[t] += red[t + st];
        __syncthreads();
    }
    if (t == 0) {
        float reg = 0.5f * red[0];
        float inv = 1.0f / 65536.0f;
        float kxx = g_acc[0] * inv, kyy = g_acc[1] * inv, kxy = g_acc[2] * inv;
        float dist = fmaxf(kxx + kyy - 2.f * kxy, 0.f);
        float knn = g_acc[4] / 256.0f;
        float anchor = g_acc[3] / 256.0f;
        float total = dist + knn + 1e-4f * reg + anchor;
        out[0] = total; out[1] = dist; out[2] = knn; out[3] = anchor;
    }
}

// ---------------- launch ----------------
extern "C" void kernel_launch(void* const* d_in, const int* in_sizes, int n_in,
                              void* d_out, int out_size) {
    const float* q  = (const float*)d_in[0];
    const float* X  = (const float*)d_in[1];
    const float* W  = (const float*)d_in[2];
    const float* b  = (const float*)d_in[3];
    const float* pw = (const float*)d_in[4];
    const int* pi   = (const int*)d_in[5];
    const int* qi   = (const int*)d_in[6];
    const int* idx  = (const int*)d_in[7];
    int N = in_sizes[1] / Dd;                       // 200000
    if (N > NxMax) N = NxMax;

    k_convX<<<(N + 7) / 8, 256>>>(X, N);
    k_tq<<<Bq, Dd>>>(q, W, b);
    k_comb<<<512, Dd>>>(X, idx);
    k_dc<<<512, 256>>>();
    for (int p = 3; p >= 0; p--) {
        k_hist<<<256, 256>>>(p);
        k_decide<<<1, 256>>>(p);
    }
    k_cntmin<<<256, 256>>>();
    k_gamma<<<1, 1>>>();
    k_mmd<<<512, 256>>>();
    dim3 gg((N + GBN - 1) / GBN, Bq / 128);
    k_gemm<<<gg, 256>>>(N);
    k_topk<<<Bq, 512>>>(N);
    k_kl<<<Bq, Dd>>>(X, pw, pi, qi);
    k_final<<<1, 256>>>(W, b, (float*)d_out);
}

// round 3
// speedup vs baseline: 1.7195x; 1.0014x over previous
#include <cuda_runtime.h>
#include <cuda_bf16.h>
#include <math.h>
#include <float.h>

#define Bq 256
#define Dd 128
#define NxMax 200000
#define Kn 50
#define TAUf 0.1f
#define EPSf 1e-8f

// ---------------- device scratch (static; no allocs) ----------------
__device__ float g_Tq[Bq * Dd];
__device__ __nv_bfloat16 g_Tqb[Bq * Dd];
__device__ float g_tqn[Bq];
__device__ float g_xn[NxMax];
__device__ __nv_bfloat16 g_Xb[(size_t)NxMax * Dd];       // 51.2 MB bf16 X
__device__ __nv_bfloat16 g_Db[(size_t)Bq * NxMax];       // 102.4 MB bf16 distances
__device__ float g_comb[512 * Dd];
__device__ float g_cn[512];
__device__ float g_Dc[512 * 512];
__device__ int   g_post[Bq * Kn];
__device__ float g_gval;
__device__ float g_acc[6];                               // kxx,kyy,kxy,anchor,kl
__device__ unsigned int g_hist[256];
__device__ unsigned int g_prefix;
__device__ unsigned int g_rem;
__device__ float g_med[2];
__device__ unsigned int g_cntle;
__device__ unsigned int g_minab;

// ---------------- X -> bf16 + row norms + zero accumulators ----------------
__global__ void k_convX(const float* __restrict__ X, int N) {
    int warp = threadIdx.x >> 5, lane = threadIdx.x & 31;
    if (blockIdx.x == 0 && threadIdx.x < 6) g_acc[threadIdx.x] = 0.f;
    int r = blockIdx.x * 8 + warp;
    if (r >= N) return;
    float4 v = *reinterpret_cast<const float4*>(X + (size_t)r * Dd + lane * 4);
    float s = v.x * v.x + v.y * v.y + v.z * v.z + v.w * v.w;
    __nv_bfloat162 h0 = __floats2bfloat162_rn(v.x, v.y);
    __nv_bfloat162 h1 = __floats2bfloat162_rn(v.z, v.w);
    uint2 packed;
    packed.x = *reinterpret_cast<unsigned*>(&h0);
    packed.y = *reinterpret_cast<unsigned*>(&h1);
    *reinterpret_cast<uint2*>(&g_Xb[(size_t)r * Dd + lane * 4]) = packed;
    for (int o = 16; o > 0; o >>= 1) s += __shfl_down_sync(0xffffffffu, s, o);
    if (lane == 0) g_xn[r] = s;
}

// ---------------- Tq = q @ W^T + b (fp32 + bf16), row norms, anchor ----------------
__global__ void k_tq(const float* __restrict__ q, const float* __restrict__ W,
                     const float* __restrict__ bb) {
    int i = blockIdx.x, t = threadIdx.x;           // 256 blocks, 128 threads
    __shared__ float qs[Dd];
    qs[t] = q[i * Dd + t];
    __syncthreads();
    const float* wr = W + t * Dd;
    float acc = bb[t];
#pragma unroll 16
    for (int c = 0; c < Dd; c++) acc = fmaf(qs[c], __ldg(&wr[c]), acc);
    g_Tq[i * Dd + t] = acc;
    g_Tqb[i * Dd + t] = __float2bfloat16(acc);
    float d = acc - qs[t];
    __shared__ float r1[Dd], r2[Dd];
    r1[t] = acc * acc; r2[t] = d * d;
    __syncthreads();
    for (int s = Dd / 2; s > 0; s >>= 1) {
        if (t < s) { r1[t] += r1[t + s]; r2[t] += r2[t + s]; }
        __syncthreads();
    }
    if (t == 0) { g_tqn[i] = r1[0]; atomicAdd(&g_acc[3], r2[0]); }
}

// ---------------- comb = [Tq ; X[idx]], norms ----------------
__global__ void k_comb(const float* __restrict__ X, const int* __restrict__ idx) {
    int i = blockIdx.x, t = threadIdx.x;           // 512 blocks, 128 threads
    const float* src = (i < Bq) ? (g_Tq + i * Dd) : (X + (size_t)idx[i - Bq] * Dd);
    float v = src[t];
    g_comb[i * Dd + t] = v;
    __shared__ float r1[Dd];
    r1[t] = v * v;
    __syncthreads();
    for (int s = Dd / 2; s > 0; s >>= 1) {
        if (t < s) r1[t] += r1[t + s];
        __syncthreads();
    }
    if (t == 0) g_cn[i] = r1[0];
}

// ---------------- Dc = sqdist(comb, comb); init select state in block 0 ----------------
__global__ void k_dc() {
    int i = blockIdx.x, t = threadIdx.x;           // 512 blocks, 256 threads
    if (i == 0) {
        g_hist[t] = 0u;
        if (t == 0) {
            g_prefix = 0u; g_rem = 131072u;        // rank of lower median (1-based)
            g_cntle = 0u; g_minab = 0x7f7fffffu;   // FLT_MAX bits
        }
    }
    __shared__ float ci[Dd];
    if (t < Dd) ci[t] = g_comb[i * Dd + t];
    __syncthreads();
    float ni = g_cn[i];
    for (int j = t; j < 512; j += 256) {
        const float* cj = g_comb + j * Dd;
        float dot = 0.f;
#pragma unroll 16
        for (int c = 0; c < Dd; c++) dot = fmaf(ci[c], cj[c], dot);
        g_Dc[i * 512 + j] = fmaxf(ni + g_cn[j] - 2.f * dot, 0.f);
    }
}

// ---------------- median radix select: histogram pass ----------------
__global__ void k_hist(int pass) {
    __shared__ unsigned int sh[256];
    for (int i = threadIdx.x; i < 256; i += blockDim.x) sh[i] = 0u;
    __syncthreads();
    unsigned int pref = g_prefix;
    unsigned int hm = (pass == 3) ? 0u : (0xFFFFFFFFu << (8 * (pass + 1)));
    for (int id = blockIdx.x * blockDim.x + threadIdx.x; id < 512 * 512;
         id += gridDim.x * blockDim.x) {
        unsigned int u = __float_as_uint(g_Dc[id]);
        if ((u & hm) == pref) atomicAdd(&sh[(u >> (8 * pass)) & 0xFFu], 1u);
    }
    __syncthreads();
    for (int i = threadIdx.x; i < 256; i += blockDim.x)
        if (sh[i]) atomicAdd(&g_hist[i], sh[i]);
}

// ---------------- parallel decide: scan 256 bins, pick bucket, reset hist ----------------
__global__ void k_decide(int pass) {
    __shared__ unsigned int s[256];
    int t = threadIdx.x;
    unsigned int c = g_hist[t];
    g_hist[t] = 0u;                                 // reset for next pass
    s[t] = c;
    __syncthreads();
    for (int off = 1; off < 256; off <<= 1) {
        unsigned int v = (t >= off) ? s[t - off] : 0u;
        __syncthreads();
        s[t] += v;
        __syncthreads();
    }
    unsigned int rem = g_rem;
    unsigned int cum = s[t];
    unsigned int prev = (t > 0) ? s[t - 1] : 0u;
    if (cum >= rem && prev < rem) {
        g_rem = rem - prev;
        unsigned int np = g_prefix | ((unsigned int)t << (8 * pass));
        g_prefix = np;
        if (pass == 0) g_med[0] = __uint_as_float(np);
    }
}

// ---------------- count <= v1, min above v1 ----------------
__global__ void k_cntmin() {
    float v1 = g_med[0];
    unsigned int c = 0;
    float mn = FLT_MAX;
    for (int id = blockIdx.x * blockDim.x + threadIdx.x; id < 512 * 512;
         id += gridDim.x * blockDim.x) {
        float v = g_Dc[id];
        if (v <= v1) c++;
        else mn = fminf(mn, v);
    }
    __shared__ unsigned int sc[256];
    __shared__ unsigned int sm[256];
    int t = threadIdx.x;
    sc[t] = c; sm[t] = __float_as_uint(mn);
    __syncthreads();
    for (int s = 128; s > 0; s >>= 1) {
        if (t < s) { sc[t] += sc[t + s]; sm[t] = min(sm[t], sm[t + s]); }
        __syncthreads();
    }
    if (t == 0) {
        atomicAdd(&g_cntle, sc[0]);
        atomicMin(&g_minab, sm[0]);
    }
}

__global__ void k_gamma() {
    float v1 = g_med[0];
    float v2 = (g_cntle >= 131073u) ? v1 : __uint_as_float(g_minab);
    float med = 0.5f * (v1 + v2);
    float sig = med * 0.5f;
    if (sig < 1e-6f) sig = 1.0f;
    g_gval = 1.0f / (sig + EPSf);
}

// ---------------- MMD kernel sums ----------------
__global__ void k_mmd() {
    float g = g_gval;
    float sxx = 0.f, syy = 0.f, sxy = 0.f;
    for (int id = blockIdx.x * blockDim.x + threadIdx.x; id < 512 * 512;
         id += gridDim.x * blockDim.x) {
        int i = id >> 9, j = id & 511;
        float e = expf(-g * g_Dc[id]);
        if (i < Bq) { if (j < Bq) sxx += e; else sxy += e; }
        else if (j >= Bq) syy += e;
    }
    __shared__ float s1[256], s2[256], s3[256];
    int t = threadIdx.x;
    s1[t] = sxx; s2[t] = syy; s3[t] = sxy;
    __syncthreads();
    for (int s = 128; s > 0; s >>= 1) {
        if (t < s) { s1[t] += s1[t + s]; s2[t] += s2[t + s]; s3[t] += s3[t + s]; }
        __syncthreads();
    }
    if (t == 0) {
        atomicAdd(&g_acc[0], s1[0]);
        atomicAdd(&g_acc[1], s2[0]);
        atomicAdd(&g_acc[2], s3[0]);
    }
}

// ---------------- bf16 tensor-core distance GEMM ----------------
// D[m][n] = max(tqn[m] + xn[n] - 2 * Tq[m,:] . X[n,:], 0), stored bf16.
// Block tile 128(M) x 128(N), K=128 staged in two 64-chunks.
// 8 warps: 4(M) x 2(N); warp tile 32 x 64 via mma.sync m16n8k16 (2 x 8 frags).
#define GBN 128
#define SSTR 72   // smem row stride in bf16 elems (64 data + 8 pad) -> conflict-free
__global__ void __launch_bounds__(256) k_gemm(int N) {
    __shared__ __align__(16) __nv_bfloat16 As[128 * SSTR];
    __shared__ __align__(16) __nv_bfloat16 Bs[128 * SSTR];
    __shared__ float tns[128], xns[128];
    int m0 = blockIdx.y * 128;
    int n0 = blockIdx.x * GBN;
    int tid = threadIdx.x;
    int warp = tid >> 5, lane = tid & 31;
    int g = lane >> 2, tg = lane & 3;
    int wm = (warp >> 1) * 32;                     // 0,32,64,96
    int wn = (warp & 1) * 64;                      // 0,64
    float acc[2][8][4];
#pragma unroll
    for (int i = 0; i < 2; i++)
#pragma unroll
        for (int j = 0; j < 8; j++)
#pragma unroll
            for (int e = 0; e < 4; e++) acc[i][j][e] = 0.f;

    if (tid < 128) {
        tns[tid] = g_tqn[m0 + tid];
        int n = n0 + tid;
        xns[tid] = (n < N) ? g_xn[n] : 0.f;
    }

#pragma unroll
    for (int kk0 = 0; kk0 < Dd; kk0 += 64) {
        __syncthreads();
        // load A tile: 128 rows x 64 cols bf16, uint4 = 8 bf16
#pragma unroll
        for (int s = tid; s < 1024; s += 256) {
            int r = s >> 3, c = (s & 7) * 8;
            *reinterpret_cast<uint4*>(&As[r * SSTR + c]) =
                *reinterpret_cast<const uint4*>(&g_Tqb[(m0 + r) * Dd + kk0 + c]);
        }
#pragma unroll
        for (int s = tid; s < 1024; s += 256) {
            int r = s >> 3, c = (s & 7) * 8;
            int n = n0 + r;
            uint4 v = make_uint4(0u, 0u, 0u, 0u);
            if (n < N) v = *reinterpret_cast<const uint4*>(&g_Xb[(size_t)n * Dd + kk0 + c]);
            *reinterpret_cast<uint4*>(&Bs[r * SSTR + c]) = v;
        }
        __syncthreads();
#pragma unroll
        for (int ks = 0; ks < 64; ks += 16) {
            unsigned a[2][4], b[8][2];
#pragma unroll
            for (int i = 0; i < 2; i++) {
                int r = wm + i * 16 + g;
                int c = ks + tg * 2;
                a[i][0] = *reinterpret_cast<unsigned*>(&As[r * SSTR + c]);
                a[i][1] = *reinterpret_cast<unsigned*>(&As[(r + 8) * SSTR + c]);
                a[i][2] = *reinterpret_cast<unsigned*>(&As[r * SSTR + c + 8]);
                a[i][3] = *reinterpret_cast<unsigned*>(&As[(r + 8) * SSTR + c + 8]);
            }
#pragma unroll
            for (int j = 0; j < 8; j++) {
                int r = wn + j * 8 + g;
                int c = ks + tg * 2;
                b[j][0] = *reinterpret_cast<unsigned*>(&Bs[r * SSTR + c]);
                b[j][1] = *reinterpret_cast<unsigned*>(&Bs[r * SSTR + c + 8]);
            }
#pragma unroll
            for (int i = 0; i < 2; i++)
#pragma unroll
                for (int j = 0; j < 8; j++)
                    asm volatile(
                        "mma.sync.aligned.m16n8k16.row.col.f32.bf16.bf16.f32 "
                        "{%0,%1,%2,%3}, {%4,%5,%6,%7}, {%8,%9}, {%0,%1,%2,%3};"
                        : "+f"(acc[i][j][0]), "+f"(acc[i][j][1]),
                          "+f"(acc[i][j][2]), "+f"(acc[i][j][3])
                        : "r"(a[i][0]), "r"(a[i][1]), "r"(a[i][2]), "r"(a[i][3]),
                          "r"(b[j][0]), "r"(b[j][1]));
        }
    }

    // epilogue: d2 = tn + xn - 2*dot, clamp, bf16x2 store
#pragma unroll
    for (int i = 0; i < 2; i++) {
        int r0 = wm + i * 16 + g;
        int m = m0 + r0;
        float tn0 = tns[r0], tn1 = tns[r0 + 8];
#pragma unroll
        for (int j = 0; j < 8; j++) {
            int cl = wn + j * 8 + tg * 2;
            int n = n0 + cl;
            if (n < N) {                           // N even, n even -> n+1 < N too
                float xa = xns[cl], xb = xns[cl + 1];
                float d00 = fmaxf(tn0 + xa - 2.f * acc[i][j][0], 0.f);
                float d01 = fmaxf(tn0 + xb - 2.f * acc[i][j][1], 0.f);
                float d10 = fmaxf(tn1 + xa - 2.f * acc[i][j][2], 0.f);
                float d11 = fmaxf(tn1 + xb - 2.f * acc[i][j][3], 0.f);
                __nv_bfloat162 p0 = __floats2bfloat162_rn(d00, d01);
                __nv_bfloat162 p1 = __floats2bfloat162_rn(d10, d11);
                *reinterpret_cast<unsigned*>(&g_Db[(size_t)m * N + n]) =
                    *reinterpret_cast<unsigned*>(&p0);
                *reinterpret_cast<unsigned*>(&g_Db[(size_t)(m + 8) * N + n]) =
                    *reinterpret_cast<unsigned*>(&p1);
            }
        }
    }
}

// ---------------- per-row top-50 via threshold stream + bitonic compaction ----------------
__device__ __forceinline__ void bitonic4096(unsigned long long* a, int tid) {
    for (int k = 2; k <= 4096; k <<= 1) {
        for (int j = k >> 1; j > 0; j >>= 1) {
            for (int i = tid; i < 4096; i += 512) {
                int ixj = i ^ j;
                if (ixj > i) {
                    bool up = ((i & k) == 0);
                    unsigned long long x = a[i], y = a[ixj];
                    if ((x > y) == up) { a[i] = y; a[ixj] = x; }
                }
            }
            __syncthreads();
        }
    }
}

__global__ void __launch_bounds__(512) k_topk(int N) {
    __shared__ unsigned long long cand[4096];
    __shared__ int cnt;
    __shared__ int csnap;
    __shared__ float curT;
    int row = blockIdx.x, tid = threadIdx.x;
    if (tid == 0) { cnt = 0; curT = FLT_MAX; }
    __syncthreads();
    const __nv_bfloat16* Drow = g_Db + (size_t)row * N;
    for (int base = 0; base < N; base += 2048) {
        float T = curT;
        int j0 = base + tid * 4;                   // 4 consecutive bf16 per thread
        if (j0 < N) {                              // N % 4 == 0 -> j0+3 < N
            uint2 u = *reinterpret_cast<const uint2*>(&Drow[j0]);
            unsigned h[4] = { u.x & 0xFFFFu, u.x >> 16, u.y & 0xFFFFu, u.y >> 16 };
#pragma unroll
            for (int e = 0; e < 4; e++) {
                float v = __uint_as_float(h[e] << 16);
                if (v < T) {
                    int p = atomicAdd(&cnt, 1);
                    cand[p] = (((unsigned long long)__float_as_uint(v)) << 32) |
                              (unsigned int)(j0 + e);
                }
            }
        }
        __syncthreads();
        if (tid == 0) csnap = cnt;
        __syncthreads();
        if (csnap > 2048) {
            for (int i = csnap + tid; i < 4096; i += 512) cand[i] = 0xFFFFFFFFFFFFFFFFULL;
            __syncthreads();
            bitonic4096(cand, tid);
            if (tid == 0) {
                cnt = Kn;
                curT = __uint_as_float((unsigned int)(cand[Kn - 1] >> 32));
            }
            __syncthreads();
        }
    }
    if (tid == 0) csnap = cnt;
    __syncthreads();
    for (int i = csnap + tid; i < 4096; i += 512) cand[i] = 0xFFFFFFFFFFFFFFFFULL;
    __syncthreads();
    bitonic4096(cand, tid);
    if (tid < Kn) g_post[row * Kn + tid] = (int)(cand[tid] & 0xFFFFFFFFu);
}

// ---------------- union-KL per row (exact fp32) ----------------
__global__ void k_kl(const float* __restrict__ X, const float* __restrict__ pw,
                     const int* __restrict__ pi, const int* __restrict__ qind) {
    int row = blockIdx.x, t = threadIdx.x;         // 256 blocks, 128 threads
    __shared__ float Tqs[Dd];
    __shared__ int cat[2 * Kn];
    __shared__ float prew[Kn], postw[Kn], l2s[Kn];
    __shared__ float pm[2 * Kn], qm[2 * Kn], mlt[2 * Kn];
    __shared__ float red[Dd];
    __shared__ float Sp, Sq;
    Tqs[t] = g_Tq[row * Dd + t];
    int qi = qind[row];
    if (t < Kn) {
        cat[t] = pi[qi * Kn + t];
        prew[t] = pw[qi * Kn + t];
        cat[Kn + t] = g_post[row * Kn + t];
    }
    __syncthreads();
    int warp = t >> 5, lane = t & 31;
    for (int k = warp; k < Kn; k += 4) {
        const float* xr = X + (size_t)cat[Kn + k] * Dd;
        float s = 0.f;
#pragma unroll
        for (int c = lane; c < Dd; c += 32) {
            float d = Tqs[c] - xr[c];
            s = fmaf(d, d, s);
        }
        for (int o = 16; o > 0; o >>= 1) s += __shfl_down_sync(0xffffffffu, s, o);
        if (lane == 0) l2s[k] = s;
    }
    __syncthreads();
    if (t == 0) {
        float mx = -FLT_MAX;
        for (int k = 0; k < Kn; k++) {
            float z = -l2s[k] * (1.f / TAUf);
            if (z > mx) mx = z;
        }
        float sm = 0.f;
        for (int k = 0; k < Kn; k++) {
            float e = expf(-l2s[k] * (1.f / TAUf) - mx);
            postw[k] = e; sm += e;
        }
        float inv = 1.f / sm;
        for (int k = 0; k < Kn; k++) postw[k] *= inv;
    }
    __syncthreads();
    if (t < 2 * Kn) {
        int id = cat[t];
        int m = 0; float pr = 0.f, qr = 0.f;
        for (int k = 0; k < 2 * Kn; k++) m += (cat[k] == id);
        for (int k = 0; k < Kn; k++) {
            if (cat[k] == id) pr += prew[k];
            if (cat[Kn + k] == id) qr += postw[k];
        }
        pm[t] = fmaxf(pr, EPSf); qm[t] = fmaxf(qr, EPSf); mlt[t] = (float)m;
    }
    __syncthreads();
    if (t == 0) {
        float a = 0.f, bs = 0.f;
        for (int m2 = 0; m2 < 2 * Kn; m2++) { a += pm[m2] / mlt[m2]; bs += qm[m2] / mlt[m2]; }
        Sp = a; Sq = bs;
    }
    __syncthreads();
    float klc = 0.f;
    if (t < 2 * Kn) {
        float p = pm[t] / Sp, q2 = qm[t] / Sq;
        klc = p * (logf(p) - logf(q2)) / mlt[t];
    }
    red[t] = klc;
    __syncthreads();
    for (int s = Dd / 2; s > 0; s >>= 1) {
        if (t < s) red[t] += red[t + s];
        __syncthreads();
    }
    if (t == 0) atomicAdd(&g_acc[4], red[0]);
}

// ---------------- finalize ----------------
__global__ void k_final(const float* __restrict__ W, const float* __restrict__ b,
                        float* __restrict__ out) {
    __shared__ float red[256];
    int t = threadIdx.x;
    float s = 0.f;
    for (int i = t; i < Dd * Dd; i += 256) { float w = W[i]; s = fmaf(w, w, s); }
    if (t < Dd) { float bv = b[t]; s = fmaf(bv, bv, s); }
    red[t] = s;
    __syncthreads();
    for (int st = 128; st > 0; st >>= 1) {
        if (t < st) red[t] += red[t + st];
        __syncthreads();
    }
    if (t == 0) {
        float reg = 0.5f * red[0];
        float inv = 1.0f / 65536.0f;
        float kxx = g_acc[0] * inv, kyy = g_acc[1] * inv, kxy = g_acc[2] * inv;
        float dist = fmaxf(kxx + kyy - 2.f * kxy, 0.f);
        float knn = g_acc[4] / 256.0f;
        float anchor = g_acc[3] / 256.0f;
        float total = dist + knn + 1e-4f * reg + anchor;
        out[0] = total; out[1] = dist; out[2] = knn; out[3] = anchor;
    }
}

// ---------------- launch ----------------
extern "C" void kernel_launch(void* const* d_in, const int* in_sizes, int n_in,
                              void* d_out, int out_size) {
    const float* q  = (const float*)d_in[0];
    const float* X  = (const float*)d_in[1];
    const float* W  = (const float*)d_in[2];
    const float* b  = (const float*)d_in[3];
    const float* pw = (const float*)d_in[4];
    const int* pi   = (const int*)d_in[5];
    const int* qi   = (const int*)d_in[6];
    const int* idx  = (const int*)d_in[7];
    int N = in_sizes[1] / Dd;                       // 200000
    if (N > NxMax) N = NxMax;

    k_convX<<<(N + 7) / 8, 256>>>(X, N);
    k_tq<<<Bq, Dd>>>(q, W, b);
    k_comb<<<512, Dd>>>(X, idx);
    k_dc<<<512, 256>>>();
    for (int p = 3; p >= 0; p--) {
        k_hist<<<256, 256>>>(p);
        k_decide<<<1, 256>>>(p);
    }
    k_cntmin<<<256, 256>>>();
    k_gamma<<<1, 1>>>();
    k_mmd<<<512, 256>>>();
    dim3 gg((N + GBN - 1) / GBN, Bq / 128);
    k_gemm<<<gg, 256>>>(N);
    k_topk<<<Bq, 512>>>(N);
    k_kl<<<Bq, Dd>>>(X, pw, pi, qi);
    k_final<<<1, 256>>>(W, b, (float*)d_out);
}

// round 4
// speedup vs baseline: 1.9180x; 1.1155x over previous
#include <cuda_runtime.h>
#include <cuda_bf16.h>
#include <math.h>
#include <float.h>

#define Bq 256
#define Dd 128
#define NxMax 200000
#define Kn 50
#define TAUf 0.1f
#define EPSf 1e-8f

// ---------------- device scratch (static; no allocs) ----------------
__device__ float g_Tq[Bq * Dd];
__device__ __nv_bfloat16 g_Tqb[Bq * Dd];
__device__ float g_tqn[Bq];
__device__ float g_xn[NxMax];
__device__ __nv_bfloat16 g_Xb[(size_t)NxMax * Dd];       // 51.2 MB bf16 X
__device__ __nv_bfloat16 g_Db[(size_t)Bq * NxMax];       // 102.4 MB bf16 distances
__device__ float g_comb[512 * Dd];
__device__ float g_cn[512];
__device__ float g_Dc[512 * 512];
__device__ int   g_post[Bq * Kn];
__device__ float g_gval;
__device__ float g_acc[6];                               // kxx,kyy,kxy,anchor,kl
__device__ unsigned g_h16[131072];                       // [0:64K) hi16 hist, [64K:128K) lo16 hist
__device__ unsigned g_b1, g_rem1, g_b2, g_rem2;
__device__ unsigned g_minab;

// ---------------- X -> bf16 + row norms + zero accumulators ----------------
__global__ void k_convX(const float* __restrict__ X, int N) {
    int warp = threadIdx.x >> 5, lane = threadIdx.x & 31;
    if (blockIdx.x == 0 && threadIdx.x < 6) g_acc[threadIdx.x] = 0.f;
    int r = blockIdx.x * 8 + warp;
    if (r >= N) return;
    float4 v = *reinterpret_cast<const float4*>(X + (size_t)r * Dd + lane * 4);
    float s = v.x * v.x + v.y * v.y + v.z * v.z + v.w * v.w;
    __nv_bfloat162 h0 = __floats2bfloat162_rn(v.x, v.y);
    __nv_bfloat162 h1 = __floats2bfloat162_rn(v.z, v.w);
    uint2 packed;
    packed.x = *reinterpret_cast<unsigned*>(&h0);
    packed.y = *reinterpret_cast<unsigned*>(&h1);
    *reinterpret_cast<uint2*>(&g_Xb[(size_t)r * Dd + lane * 4]) = packed;
    for (int o = 16; o > 0; o >>= 1) s += __shfl_down_sync(0xffffffffu, s, o);
    if (lane == 0) g_xn[r] = s;
}

// ---------------- Tq = q @ W^T + b (fp32 + bf16), norms, anchor; init median state ----
__global__ void k_tq(const float* __restrict__ q, const float* __restrict__ W,
                     const float* __restrict__ bb) {
    int i = blockIdx.x, t = threadIdx.x;           // 256 blocks, 128 threads
    int gid = i * 128 + t;                          // 32768 threads: zero hists
#pragma unroll
    for (int z = gid; z < 131072; z += 32768) g_h16[z] = 0u;
    if (gid == 0) g_minab = 0xFFFFFFFFu;
    __shared__ float qs[Dd];
    qs[t] = q[i * Dd + t];
    __syncthreads();
    const float* wr = W + t * Dd;
    float acc = bb[t];
#pragma unroll 16
    for (int c = 0; c < Dd; c++) acc = fmaf(qs[c], __ldg(&wr[c]), acc);
    g_Tq[i * Dd + t] = acc;
    g_Tqb[i * Dd + t] = __float2bfloat16(acc);
    float d = acc - qs[t];
    __shared__ float r1[Dd], r2[Dd];
    r1[t] = acc * acc; r2[t] = d * d;
    __syncthreads();
    for (int s = Dd / 2; s > 0; s >>= 1) {
        if (t < s) { r1[t] += r1[t + s]; r2[t] += r2[t + s]; }
        __syncthreads();
    }
    if (t == 0) { g_tqn[i] = r1[0]; atomicAdd(&g_acc[3], r2[0]); }
}

// ---------------- comb = [Tq ; X[idx]], norms ----------------
__global__ void k_comb(const float* __restrict__ X, const int* __restrict__ idx) {
    int i = blockIdx.x, t = threadIdx.x;           // 512 blocks, 128 threads
    const float* src = (i < Bq) ? (g_Tq + i * Dd) : (X + (size_t)idx[i - Bq] * Dd);
    float v = src[t];
    g_comb[i * Dd + t] = v;
    __shared__ float r1[Dd];
    r1[t] = v * v;
    __syncthreads();
    for (int s = Dd / 2; s > 0; s >>= 1) {
        if (t < s) r1[t] += r1[t + s];
        __syncthreads();
    }
    if (t == 0) g_cn[i] = r1[0];
}

// ---------------- Dc = sqdist(comb, comb), tiled; fused hi16 histogram ----------------
#define DCB 64
#define DCS 68   // smem row stride (64 + 4 pad)
__global__ void __launch_bounds__(256) k_dc2() {
    __shared__ float AsT[128][DCS];                 // [k][row]
    __shared__ float BsT[128][DCS];
    int i0 = blockIdx.y * DCB, j0 = blockIdx.x * DCB;
    int tid = threadIdx.x;
    // fill transposed tiles: task s -> (k, rowgroup-of-4); coalesced gmem, STS.128 smem
#pragma unroll
    for (int s = tid; s < 2048; s += 256) {
        int k = s & 127, r4 = (s >> 7) * 4;
        float4 va, vb;
        va.x = g_comb[(i0 + r4 + 0) * Dd + k];
        va.y = g_comb[(i0 + r4 + 1) * Dd + k];
        va.z = g_comb[(i0 + r4 + 2) * Dd + k];
        va.w = g_comb[(i0 + r4 + 3) * Dd + k];
        *reinterpret_cast<float4*>(&AsT[k][r4]) = va;
        vb.x = g_comb[(j0 + r4 + 0) * Dd + k];
        vb.y = g_comb[(j0 + r4 + 1) * Dd + k];
        vb.z = g_comb[(j0 + r4 + 2) * Dd + k];
        vb.w = g_comb[(j0 + r4 + 3) * Dd + k];
        *reinterpret_cast<float4*>(&BsT[k][r4]) = vb;
    }
    __syncthreads();
    int tr = tid >> 4, tc = tid & 15;
    float acc[4][4];
#pragma unroll
    for (int i = 0; i < 4; i++)
#pragma unroll
        for (int j = 0; j < 4; j++) acc[i][j] = 0.f;
#pragma unroll 4
    for (int k = 0; k < 128; k++) {
        float4 a = *reinterpret_cast<const float4*>(&AsT[k][tr * 4]);
        float4 b = *reinterpret_cast<const float4*>(&BsT[k][tc * 4]);
        float av[4] = {a.x, a.y, a.z, a.w};
        float bv[4] = {b.x, b.y, b.z, b.w};
#pragma unroll
        for (int i = 0; i < 4; i++)
#pragma unroll
            for (int j = 0; j < 4; j++) acc[i][j] = fmaf(av[i], bv[j], acc[i][j]);
    }
    float cni[4], cnj[4];
#pragma unroll
    for (int e = 0; e < 4; e++) { cni[e] = g_cn[i0 + tr * 4 + e]; cnj[e] = g_cn[j0 + tc * 4 + e]; }
#pragma unroll
    for (int i = 0; i < 4; i++) {
        int row = i0 + tr * 4 + i;
#pragma unroll
        for (int j = 0; j < 4; j++) {
            float v = fmaxf(cni[i] + cnj[j] - 2.f * acc[i][j], 0.f);
            g_Dc[row * 512 + j0 + tc * 4 + j] = v;
            atomicAdd(&g_h16[__float_as_uint(v) >> 16], 1u);
        }
    }
}

// ---------------- decide hi16 buckets for ranks 131072, 131073 ----------------
__global__ void __launch_bounds__(1024) k_decide16() {
    __shared__ unsigned s[1024];
    int t = threadIdx.x;
    unsigned part = 0;
#pragma unroll 8
    for (int i = 0; i < 64; i++) part += g_h16[t * 64 + i];
    s[t] = part;
    __syncthreads();
    for (int off = 1; off < 1024; off <<= 1) {
        unsigned v = (t >= off) ? s[t - off] : 0u;
        __syncthreads();
        s[t] += v;
        __syncthreads();
    }
    unsigned before = (t > 0) ? s[t - 1] : 0u;
    unsigned after = s[t];
#pragma unroll
    for (int which = 0; which < 2; which++) {
        unsigned rank = 131072u + (unsigned)which;
        if (before < rank && rank <= after) {
            unsigned cum = before;
            for (int i = 0; i < 64; i++) {
                unsigned c = g_h16[t * 64 + i];
                if (cum + c >= rank) {
                    if (which == 0) { g_b1 = (unsigned)(t * 64 + i); g_rem1 = rank - cum; }
                    else            { g_b2 = (unsigned)(t * 64 + i); g_rem2 = rank - cum; }
                    break;
                }
                cum += c;
            }
        }
    }
}

// ---------------- lo16 histogram within bucket b1; min lo16 in bucket b2 ----------------
__global__ void k_histlow() {
    unsigned b1 = g_b1, b2 = g_b2;
    unsigned lm = 0xFFFFFFFFu;
    for (int id = blockIdx.x * blockDim.x + threadIdx.x; id < 512 * 512;
         id += gridDim.x * blockDim.x) {
        unsigned u = __float_as_uint(g_Dc[id]);
        unsigned hi = u >> 16;
        if (hi == b1) atomicAdd(&g_h16[65536 + (u & 0xFFFFu)], 1u);
        else if (hi == b2) lm = min(lm, u & 0xFFFFu);
    }
    for (int o = 16; o > 0; o >>= 1) lm = min(lm, __shfl_down_sync(0xffffffffu, lm, o));
    __shared__ unsigned sm[8];
    int w = threadIdx.x >> 5;
    if ((threadIdx.x & 31) == 0) sm[w] = lm;
    __syncthreads();
    if (threadIdx.x == 0) {
        unsigned m = sm[0];
        for (int i = 1; i < 8; i++) m = min(m, sm[i]);
        if (m != 0xFFFFFFFFu) atomicMin(&g_minab, m);
    }
}

// ---------------- decide lo16, compute gamma ----------------
__global__ void __launch_bounds__(1024) k_decidelow() {
    __shared__ unsigned s[1024];
    __shared__ unsigned shv[2];
    int t = threadIdx.x;
    unsigned part = 0;
#pragma unroll 8
    for (int i = 0; i < 64; i++) part += g_h16[65536 + t * 64 + i];
    s[t] = part;
    __syncthreads();
    for (int off = 1; off < 1024; off <<= 1) {
        unsigned v = (t >= off) ? s[t - off] : 0u;
        __syncthreads();
        s[t] += v;
        __syncthreads();
    }
    unsigned before = (t > 0) ? s[t - 1] : 0u;
    unsigned after = s[t];
    unsigned b1 = g_b1, b2 = g_b2;
    bool same = (b1 == b2);
    unsigned ranks[2] = { g_rem1, same ? g_rem2 : 0u };
#pragma unroll
    for (int which = 0; which < 2; which++) {
        if (which == 1 && !same) break;
        unsigned rank = ranks[which];
        if (before < rank && rank <= after) {
            unsigned cum = before;
            for (int i = 0; i < 64; i++) {
                unsigned c = g_h16[65536 + t * 64 + i];
                if (cum + c >= rank) { shv[which] = (unsigned)(t * 64 + i); break; }
                cum += c;
            }
        }
    }
    __syncthreads();
    if (t == 0) {
        unsigned v1 = (b1 << 16) | shv[0];
        unsigned v2 = same ? ((b1 << 16) | shv[1]) : ((b2 << 16) | g_minab);
        float med = 0.5f * (__uint_as_float(v1) + __uint_as_float(v2));
        float sig = med * 0.5f;
        if (sig < 1e-6f) sig = 1.0f;
        g_gval = 1.0f / (sig + EPSf);
    }
}

// ---------------- MMD kernel sums ----------------
__global__ void k_mmd() {
    float g = g_gval;
    float sxx = 0.f, syy = 0.f, sxy = 0.f;
    for (int id = blockIdx.x * blockDim.x + threadIdx.x; id < 512 * 512;
         id += gridDim.x * blockDim.x) {
        int i = id >> 9, j = id & 511;
        float e = expf(-g * g_Dc[id]);
        if (i < Bq) { if (j < Bq) sxx += e; else sxy += e; }
        else if (j >= Bq) syy += e;
    }
    __shared__ float s1[256], s2[256], s3[256];
    int t = threadIdx.x;
    s1[t] = sxx; s2[t] = syy; s3[t] = sxy;
    __syncthreads();
    for (int s = 128; s > 0; s >>= 1) {
        if (t < s) { s1[t] += s1[t + s]; s2[t] += s2[t + s]; s3[t] += s3[t + s]; }
        __syncthreads();
    }
    if (t == 0) {
        atomicAdd(&g_acc[0], s1[0]);
        atomicAdd(&g_acc[1], s2[0]);
        atomicAdd(&g_acc[2], s3[0]);
    }
}

// ---------------- bf16 tensor-core distance GEMM ----------------
#define GBN 128
#define SSTR 72
__global__ void __launch_bounds__(256) k_gemm(int N) {
    __shared__ __align__(16) __nv_bfloat16 As[128 * SSTR];
    __shared__ __align__(16) __nv_bfloat16 Bs[128 * SSTR];
    __shared__ float tns[128], xns[128];
    int m0 = blockIdx.y * 128;
    int n0 = blockIdx.x * GBN;
    int tid = threadIdx.x;
    int warp = tid >> 5, lane = tid & 31;
    int g = lane >> 2, tg = lane & 3;
    int wm = (warp >> 1) * 32;
    int wn = (warp & 1) * 64;
    float acc[2][8][4];
#pragma unroll
    for (int i = 0; i < 2; i++)
#pragma unroll
        for (int j = 0; j < 8; j++)
#pragma unroll
            for (int e = 0; e < 4; e++) acc[i][j][e] = 0.f;

    if (tid < 128) {
        tns[tid] = g_tqn[m0 + tid];
        int n = n0 + tid;
        xns[tid] = (n < N) ? g_xn[n] : 0.f;
    }

#pragma unroll
    for (int kk0 = 0; kk0 < Dd; kk0 += 64) {
        __syncthreads();
#pragma unroll
        for (int s = tid; s < 1024; s += 256) {
            int r = s >> 3, c = (s & 7) * 8;
            *reinterpret_cast<uint4*>(&As[r * SSTR + c]) =
                *reinterpret_cast<const uint4*>(&g_Tqb[(m0 + r) * Dd + kk0 + c]);
        }
#pragma unroll
        for (int s = tid; s < 1024; s += 256) {
            int r = s >> 3, c = (s & 7) * 8;
            int n = n0 + r;
            uint4 v = make_uint4(0u, 0u, 0u, 0u);
            if (n < N) v = *reinterpret_cast<const uint4*>(&g_Xb[(size_t)n * Dd + kk0 + c]);
            *reinterpret_cast<uint4*>(&Bs[r * SSTR + c]) = v;
        }
        __syncthreads();
#pragma unroll
        for (int ks = 0; ks < 64; ks += 16) {
            unsigned a[2][4], b[8][2];
#pragma unroll
            for (int i = 0; i < 2; i++) {
                int r = wm + i * 16 + g;
                int c = ks + tg * 2;
                a[i][0] = *reinterpret_cast<unsigned*>(&As[r * SSTR + c]);
                a[i][1] = *reinterpret_cast<unsigned*>(&As[(r + 8) * SSTR + c]);
                a[i][2] = *reinterpret_cast<unsigned*>(&As[r * SSTR + c + 8]);
                a[i][3] = *reinterpret_cast<unsigned*>(&As[(r + 8) * SSTR + c + 8]);
            }
#pragma unroll
            for (int j = 0; j < 8; j++) {
                int r = wn + j * 8 + g;
                int c = ks + tg * 2;
                b[j][0] = *reinterpret_cast<unsigned*>(&Bs[r * SSTR + c]);
                b[j][1] = *reinterpret_cast<unsigned*>(&Bs[r * SSTR + c + 8]);
            }
#pragma unroll
            for (int i = 0; i < 2; i++)
#pragma unroll
                for (int j = 0; j < 8; j++)
                    asm volatile(
                        "mma.sync.aligned.m16n8k16.row.col.f32.bf16.bf16.f32 "
                        "{%0,%1,%2,%3}, {%4,%5,%6,%7}, {%8,%9}, {%0,%1,%2,%3};"
                        : "+f"(acc[i][j][0]), "+f"(acc[i][j][1]),
                          "+f"(acc[i][j][2]), "+f"(acc[i][j][3])
                        : "r"(a[i][0]), "r"(a[i][1]), "r"(a[i][2]), "r"(a[i][3]),
                          "r"(b[j][0]), "r"(b[j][1]));
        }
    }

#pragma unroll
    for (int i = 0; i < 2; i++) {
        int r0 = wm + i * 16 + g;
        int m = m0 + r0;
        float tn0 = tns[r0], tn1 = tns[r0 + 8];
#pragma unroll
        for (int j = 0; j < 8; j++) {
            int cl = wn + j * 8 + tg * 2;
            int n = n0 + cl;
            if (n < N) {
                float xa = xns[cl], xb = xns[cl + 1];
                float d00 = fmaxf(tn0 + xa - 2.f * acc[i][j][0], 0.f);
                float d01 = fmaxf(tn0 + xb - 2.f * acc[i][j][1], 0.f);
                float d10 = fmaxf(tn1 + xa - 2.f * acc[i][j][2], 0.f);
                float d11 = fmaxf(tn1 + xb - 2.f * acc[i][j][3], 0.f);
                __nv_bfloat162 p0 = __floats2bfloat162_rn(d00, d01);
                __nv_bfloat162 p1 = __floats2bfloat162_rn(d10, d11);
                *reinterpret_cast<unsigned*>(&g_Db[(size_t)m * N + n]) =
                    *reinterpret_cast<unsigned*>(&p0);
                *reinterpret_cast<unsigned*>(&g_Db[(size_t)(m + 8) * N + n]) =
                    *reinterpret_cast<unsigned*>(&p1);
            }
        }
    }
}

// ---------------- per-row top-50 via threshold stream + bitonic compaction ----------------
__device__ __forceinline__ void bitonic4096(unsigned long long* a, int tid) {
    for (int k = 2; k <= 4096; k <<= 1) {
        for (int j = k >> 1; j > 0; j >>= 1) {
            for (int i = tid; i < 4096; i += 512) {
                int ixj = i ^ j;
                if (ixj > i) {
                    bool up = ((i & k) == 0);
                    unsigned long long x = a[i], y = a[ixj];
                    if ((x > y) == up) { a[i] = y; a[ixj] = x; }
                }
            }
            __syncthreads();
        }
    }
}

__global__ void __launch_bounds__(512) k_topk(int N) {
    __shared__ unsigned long long cand[4096];
    __shared__ int cnt;
    __shared__ int csnap;
    __shared__ float curT;
    int row = blockIdx.x, tid = threadIdx.x;
    if (tid == 0) { cnt = 0; curT = FLT_MAX; }
    __syncthreads();
    const __nv_bfloat16* Drow = g_Db + (size_t)row * N;
    for (int base = 0; base < N; base += 4096) {
        float T = curT;
        int j0 = base + tid * 8;                   // 8 consecutive bf16 per thread
        if (j0 < N) {                              // N % 8 == 0 -> j0+7 < N
            uint4 u = *reinterpret_cast<const uint4*>(&Drow[j0]);
            unsigned w[4] = { u.x, u.y, u.z, u.w };
#pragma unroll
            for (int e = 0; e < 4; e++) {
                unsigned h0 = w[e] & 0xFFFFu, h1 = w[e] >> 16;
                float v0 = __uint_as_float(h0 << 16);
                float v1 = __uint_as_float(h1 << 16);
                if (v0 < T) {
                    int p = atomicAdd(&cnt, 1);
                    if (p < 4096)
                        cand[p] = (((unsigned long long)__float_as_uint(v0)) << 32) |
                                  (unsigned int)(j0 + e * 2);
                }
                if (v1 < T) {
                    int p = atomicAdd(&cnt, 1);
                    if (p < 4096)
                        cand[p] = (((unsigned long long)__float_as_uint(v1)) << 32) |
                                  (unsigned int)(j0 + e * 2 + 1);
                }
            }
        }
        __syncthreads();
        if (tid == 0) csnap = cnt;
        __syncthreads();
        if (csnap > 2048) {
            for (int i = csnap + tid; i < 4096; i += 512) cand[i] = 0xFFFFFFFFFFFFFFFFULL;
            __syncthreads();
            bitonic4096(cand, tid);
            if (tid == 0) {
                cnt = Kn;
                curT = __uint_as_float((unsigned int)(cand[Kn - 1] >> 32));
            }
            __syncthreads();
        }
    }
    if (tid == 0) csnap = cnt;
    __syncthreads();
    for (int i = csnap + tid; i < 4096; i += 512) cand[i] = 0xFFFFFFFFFFFFFFFFULL;
    __syncthreads();
    bitonic4096(cand, tid);
    if (tid < Kn) g_post[row * Kn + tid] = (int)(cand[tid] & 0xFFFFFFFFu);
}

// ---------------- union-KL per row (exact fp32) ----------------
__global__ void k_kl(const float* __restrict__ X, const float* __restrict__ pw,
                     const int* __restrict__ pi, const int* __restrict__ qind) {
    int row = blockIdx.x, t = threadIdx.x;         // 256 blocks, 128 threads
    __shared__ float Tqs[Dd];
    __shared__ int cat[2 * Kn];
    __shared__ float prew[Kn], postw[Kn], l2s[Kn];
    __shared__ float pm[2 * Kn], qm[2 * Kn], mlt[2 * Kn];
    __shared__ float red[Dd];
    __shared__ float Sp, Sq;
    Tqs[t] = g_Tq[row * Dd + t];
    int qi = qind[row];
    if (t < Kn) {
        cat[t] = pi[qi * Kn + t];
        prew[t] = pw[qi * Kn + t];
        cat[Kn + t] = g_post[row * Kn + t];
    }
    __syncthreads();
    int warp = t >> 5, lane = t & 31;
    for (int k = warp; k < Kn; k += 4) {
        const float* xr = X + (size_t)cat[Kn + k] * Dd;
        float s = 0.f;
#pragma unroll
        for (int c = lane; c < Dd; c += 32) {
            float d = Tqs[c] - xr[c];
            s = fmaf(d, d, s);
        }
        for (int o = 16; o > 0; o >>= 1) s += __shfl_down_sync(0xffffffffu, s, o);
        if (lane == 0) l2s[k] = s;
    }
    __syncthreads();
    if (t == 0) {
        float mx = -FLT_MAX;
        for (int k = 0; k < Kn; k++) {
            float z = -l2s[k] * (1.f / TAUf);
            if (z > mx) mx = z;
        }
        float sm = 0.f;
        for (int k = 0; k < Kn; k++) {
            float e = expf(-l2s[k] * (1.f / TAUf) - mx);
            postw[k] = e; sm += e;
        }
        float inv = 1.f / sm;
        for (int k = 0; k < Kn; k++) postw[k] *= inv;
    }
    __syncthreads();
    if (t < 2 * Kn) {
        int id = cat[t];
        int m = 0; float pr = 0.f, qr = 0.f;
        for (int k = 0; k < 2 * Kn; k++) m += (cat[k] == id);
        for (int k = 0; k < Kn; k++) {
            if (cat[k] == id) pr += prew[k];
            if (cat[Kn + k] == id) qr += postw[k];
        }
        pm[t] = fmaxf(pr, EPSf); qm[t] = fmaxf(qr, EPSf); mlt[t] = (float)m;
    }
    __syncthreads();
    if (t == 0) {
        float a = 0.f, bs = 0.f;
        for (int m2 = 0; m2 < 2 * Kn; m2++) { a += pm[m2] / mlt[m2]; bs += qm[m2] / mlt[m2]; }
        Sp = a; Sq = bs;
    }
    __syncthreads();
    float klc = 0.f;
    if (t < 2 * Kn) {
        float p = pm[t] / Sp, q2 = qm[t] / Sq;
        klc = p * (logf(p) - logf(q2)) / mlt[t];
    }
    red[t] = klc;
    __syncthreads();
    for (int s = Dd / 2; s > 0; s >>= 1) {
        if (t < s) red[t] += red[t + s];
        __syncthreads();
    }
    if (t == 0) atomicAdd(&g_acc[4], red[0]);
}

// ---------------- finalize ----------------
__global__ void k_final(const float* __restrict__ W, const float* __restrict__ b,
                        float* __restrict__ out) {
    __shared__ float red[256];
    int t = threadIdx.x;
    float s = 0.f;
    for (int i = t; i < Dd * Dd; i += 256) { float w = W[i]; s = fmaf(w, w, s); }
    if (t < Dd) { float bv = b[t]; s = fmaf(bv, bv, s); }
    red[t] = s;
    __syncthreads();
    for (int st = 128; st > 0; st >>= 1) {
        if (t < st) red[t] += red[t + st];
        __syncthreads();
    }
    if (t == 0) {
        float reg = 0.5f * red[0];
        float inv = 1.0f / 65536.0f;
        float kxx = g_acc[0] * inv, kyy = g_acc[1] * inv, kxy = g_acc[2] * inv;
        float dist = fmaxf(kxx + kyy - 2.f * kxy, 0.f);
        float knn = g_acc[4] / 256.0f;
        float anchor = g_acc[3] / 256.0f;
        float total = dist + knn + 1e-4f * reg + anchor;
        out[0] = total; out[1] = dist; out[2] = knn; out[3] = anchor;
    }
}

// ---------------- launch ----------------
extern "C" void kernel_launch(void* const* d_in, const int* in_sizes, int n_in,
                              void* d_out, int out_size) {
    const float* q  = (const float*)d_in[0];
    const float* X  = (const float*)d_in[1];
    const float* W  = (const float*)d_in[2];
    const float* b  = (const float*)d_in[3];
    const float* pw = (const float*)d_in[4];
    const int* pi   = (const int*)d_in[5];
    const int* qi   = (const int*)d_in[6];
    const int* idx  = (const int*)d_in[7];
    int N = in_sizes[1] / Dd;                       // 200000
    if (N > NxMax) N = NxMax;

    k_convX<<<(N + 7) / 8, 256>>>(X, N);
    k_tq<<<Bq, Dd>>>(q, W, b);
    k_comb<<<512, Dd>>>(X, idx);
    dim3 dg(512 / DCB, 512 / DCB);
    k_dc2<<<dg, 256>>>();
    k_decide16<<<1, 1024>>>();
    k_histlow<<<256, 256>>>();
    k_decidelow<<<1, 1024>>>();
    k_mmd<<<512, 256>>>();
    dim3 gg((N + GBN - 1) / GBN, Bq / 128);
    k_gemm<<<gg, 256>>>(N);
    k_topk<<<Bq, 512>>>(N);
    k_kl<<<Bq, Dd>>>(X, pw, pi, qi);
    k_final<<<1, 256>>>(W, b, (float*)d_out);
}

// round 5
// speedup vs baseline: 2.0095x; 1.0477x over previous
#include <cuda_runtime.h>
#include <cuda_bf16.h>
#include <math.h>
#include <float.h>

#define Bq 256
#define Dd 128
#define NxMax 200000
#define Kn 50
#define TAUf 0.1f
#define EPSf 1e-8f
#define NTpad 1600
typedef unsigned long long ull;

// ---------------- device scratch (static; no allocs) ----------------
__device__ float g_Tq[Bq * Dd];
__device__ __nv_bfloat16 g_Tqb[Bq * Dd];
__device__ float g_tqn[Bq];
__device__ float g_xn[NxMax];
__device__ __nv_bfloat16 g_Xb[(size_t)NxMax * Dd];       // 51.2 MB bf16 X
__device__ __nv_bfloat16 g_Db[(size_t)Bq * NxMax];       // 102.4 MB bf16 distances
__device__ float g_tmin[(size_t)Bq * NTpad];             // per-(row,128-tile) min
__device__ float g_comb[512 * Dd];
__device__ float g_cn[512];
__device__ float g_Dc[512 * 512];
__device__ int   g_post[Bq * Kn];
__device__ float g_gval;
__device__ float g_acc[6];
__device__ unsigned g_h16[131072];
__device__ unsigned g_b1, g_rem1, g_b2, g_rem2;
__device__ unsigned g_minab;

// ---------------- X -> bf16 + row norms + zero accumulators ----------------
__global__ void k_convX(const float* __restrict__ X, int N) {
    int warp = threadIdx.x >> 5, lane = threadIdx.x & 31;
    if (blockIdx.x == 0 && threadIdx.x < 6) g_acc[threadIdx.x] = 0.f;
    int r = blockIdx.x * 8 + warp;
    if (r >= N) return;
    float4 v = *reinterpret_cast<const float4*>(X + (size_t)r * Dd + lane * 4);
    float s = v.x * v.x + v.y * v.y + v.z * v.z + v.w * v.w;
    __nv_bfloat162 h0 = __floats2bfloat162_rn(v.x, v.y);
    __nv_bfloat162 h1 = __floats2bfloat162_rn(v.z, v.w);
    uint2 packed;
    packed.x = *reinterpret_cast<unsigned*>(&h0);
    packed.y = *reinterpret_cast<unsigned*>(&h1);
    *reinterpret_cast<uint2*>(&g_Xb[(size_t)r * Dd + lane * 4]) = packed;
    for (int o = 16; o > 0; o >>= 1) s += __shfl_down_sync(0xffffffffu, s, o);
    if (lane == 0) g_xn[r] = s;
}

// ---------------- Tq = q @ W^T + b, norms, anchor; zero median hists ----------------
__global__ void k_tq(const float* __restrict__ q, const float* __restrict__ W,
                     const float* __restrict__ bb) {
    int i = blockIdx.x, t = threadIdx.x;
    int gid = i * 128 + t;
#pragma unroll
    for (int z = gid; z < 131072; z += 32768) g_h16[z] = 0u;
    if (gid == 0) g_minab = 0xFFFFFFFFu;
    __shared__ float qs[Dd];
    qs[t] = q[i * Dd + t];
    __syncthreads();
    const float* wr = W + t * Dd;
    float acc = bb[t];
#pragma unroll 16
    for (int c = 0; c < Dd; c++) acc = fmaf(qs[c], __ldg(&wr[c]), acc);
    g_Tq[i * Dd + t] = acc;
    g_Tqb[i * Dd + t] = __float2bfloat16(acc);
    float d = acc - qs[t];
    __shared__ float r1[Dd], r2[Dd];
    r1[t] = acc * acc; r2[t] = d * d;
    __syncthreads();
    for (int s = Dd / 2; s > 0; s >>= 1) {
        if (t < s) { r1[t] += r1[t + s]; r2[t] += r2[t + s]; }
        __syncthreads();
    }
    if (t == 0) { g_tqn[i] = r1[0]; atomicAdd(&g_acc[3], r2[0]); }
}

// ---------------- comb = [Tq ; X[idx]], norms ----------------
__global__ void k_comb(const float* __restrict__ X, const int* __restrict__ idx) {
    int i = blockIdx.x, t = threadIdx.x;
    const float* src = (i < Bq) ? (g_Tq + i * Dd) : (X + (size_t)idx[i - Bq] * Dd);
    float v = src[t];
    g_comb[i * Dd + t] = v;
    __shared__ float r1[Dd];
    r1[t] = v * v;
    __syncthreads();
    for (int s = Dd / 2; s > 0; s >>= 1) {
        if (t < s) r1[t] += r1[t + s];
        __syncthreads();
    }
    if (t == 0) g_cn[i] = r1[0];
}

// ---------------- bf16 tensor-core distance GEMM (4th launch -> ncu) ----------------
// D[m][n] = max(tqn[m]+xn[n]-2*Tq.X, 0) -> bf16 Db; also per-(row,tile) min -> g_tmin.
#define SSTR 72
#define DSTR 136
__global__ void __launch_bounds__(256) k_gemm(int N) {
    __shared__ __align__(16) __nv_bfloat16 sm[2 * 128 * SSTR];  // A | B (one stage)
    __shared__ float tns[128], xns[128];
    __shared__ unsigned minu[128];
    __nv_bfloat16* smA = sm;
    __nv_bfloat16* smB = sm + 128 * SSTR;
    int m0 = blockIdx.y * 128;
    int n0 = blockIdx.x * 128;
    int tid = threadIdx.x;
    int warp = tid >> 5, lane = tid & 31;
    int g = lane >> 2, tg = lane & 3;
    int wm = (warp >> 1) * 32;
    int wn = (warp & 1) * 64;
    float acc[2][8][4];
#pragma unroll
    for (int i = 0; i < 2; i++)
#pragma unroll
        for (int j = 0; j < 8; j++)
#pragma unroll
            for (int e = 0; e < 4; e++) acc[i][j][e] = 0.f;

    // prefetch both K-chunks into registers (MLP=16)
    uint4 pa0[4], pb0[4], pa1[4], pb1[4];
#pragma unroll
    for (int u = 0; u < 4; u++) {
        int s = tid + u * 256;
        int r = s >> 3, c = (s & 7) * 8;
        pa0[u] = *reinterpret_cast<const uint4*>(&g_Tqb[(m0 + r) * Dd + c]);
        pa1[u] = *reinterpret_cast<const uint4*>(&g_Tqb[(m0 + r) * Dd + 64 + c]);
        int n = n0 + r;
        uint4 z = make_uint4(0u, 0u, 0u, 0u);
        pb0[u] = z; pb1[u] = z;
        if (n < N) {
            const __nv_bfloat16* bp = &g_Xb[(size_t)n * Dd];
            pb0[u] = *reinterpret_cast<const uint4*>(&bp[c]);
            pb1[u] = *reinterpret_cast<const uint4*>(&bp[64 + c]);
        }
    }
    if (tid < 128) {
        tns[tid] = g_tqn[m0 + tid];
        int n = n0 + tid;
        xns[tid] = (n < N) ? g_xn[n] : 0.f;
        minu[tid] = 0x7f800000u;                   // +INF
    }

#pragma unroll
    for (int st = 0; st < 2; st++) {
        // store this stage
#pragma unroll
        for (int u = 0; u < 4; u++) {
            int s = tid + u * 256;
            int r = s >> 3, c = (s & 7) * 8;
            *reinterpret_cast<uint4*>(&smA[r * SSTR + c]) = st ? pa1[u] : pa0[u];
            *reinterpret_cast<uint4*>(&smB[r * SSTR + c]) = st ? pb1[u] : pb0[u];
        }
        __syncthreads();
#pragma unroll
        for (int ks = 0; ks < 64; ks += 16) {
            unsigned a[2][4], b[8][2];
#pragma unroll
            for (int i = 0; i < 2; i++) {
                int r = wm + i * 16 + g;
                int c = ks + tg * 2;
                a[i][0] = *reinterpret_cast<unsigned*>(&smA[r * SSTR + c]);
                a[i][1] = *reinterpret_cast<unsigned*>(&smA[(r + 8) * SSTR + c]);
                a[i][2] = *reinterpret_cast<unsigned*>(&smA[r * SSTR + c + 8]);
                a[i][3] = *reinterpret_cast<unsigned*>(&smA[(r + 8) * SSTR + c + 8]);
            }
#pragma unroll
            for (int j = 0; j < 8; j++) {
                int r = wn + j * 8 + g;
                int c = ks + tg * 2;
                b[j][0] = *reinterpret_cast<unsigned*>(&smB[r * SSTR + c]);
                b[j][1] = *reinterpret_cast<unsigned*>(&smB[r * SSTR + c + 8]);
            }
#pragma unroll
            for (int i = 0; i < 2; i++)
#pragma unroll
                for (int j = 0; j < 8; j++)
                    asm volatile(
                        "mma.sync.aligned.m16n8k16.row.col.f32.bf16.bf16.f32 "
                        "{%0,%1,%2,%3}, {%4,%5,%6,%7}, {%8,%9}, {%0,%1,%2,%3};"
                        : "+f"(acc[i][j][0]), "+f"(acc[i][j][1]),
                          "+f"(acc[i][j][2]), "+f"(acc[i][j][3])
                        : "r"(a[i][0]), "r"(a[i][1]), "r"(a[i][2]), "r"(a[i][3]),
                          "r"(b[j][0]), "r"(b[j][1]));
        }
        __syncthreads();
    }

    // epilogue: pack bf16 d2 into smem (overlay), track per-row mins
    __nv_bfloat16* Ds = sm;                        // 128*DSTR = 17408 <= 18432 elems
#pragma unroll
    for (int i = 0; i < 2; i++) {
        int r0 = wm + i * 16 + g;
        float tn0 = tns[r0], tn1 = tns[r0 + 8];
        float rm0 = FLT_MAX, rm1 = FLT_MAX;
#pragma unroll
        for (int j = 0; j < 8; j++) {
            int cl = wn + j * 8 + tg * 2;
            int n = n0 + cl;
            if (n < N) {
                float xa = xns[cl], xb = xns[cl + 1];
                float d00 = fmaxf(tn0 + xa - 2.f * acc[i][j][0], 0.f);
                float d01 = fmaxf(tn0 + xb - 2.f * acc[i][j][1], 0.f);
                float d10 = fmaxf(tn1 + xa - 2.f * acc[i][j][2], 0.f);
                float d11 = fmaxf(tn1 + xb - 2.f * acc[i][j][3], 0.f);
                __nv_bfloat162 p0 = __floats2bfloat162_rn(d00, d01);
                __nv_bfloat162 p1 = __floats2bfloat162_rn(d10, d11);
                float2 f0 = __bfloat1622float2(p0);
                float2 f1 = __bfloat1622float2(p1);
                rm0 = fminf(rm0, fminf(f0.x, f0.y));
                rm1 = fminf(rm1, fminf(f1.x, f1.y));
                *reinterpret_cast<unsigned*>(&Ds[r0 * DSTR + cl]) =
                    *reinterpret_cast<unsigned*>(&p0);
                *reinterpret_cast<unsigned*>(&Ds[(r0 + 8) * DSTR + cl]) =
                    *reinterpret_cast<unsigned*>(&p1);
            }
        }
        if (rm0 < FLT_MAX) atomicMin(&minu[r0], __float_as_uint(rm0));
        if (rm1 < FLT_MAX) atomicMin(&minu[r0 + 8], __float_as_uint(rm1));
    }
    __syncthreads();
    // coalesced drain to gmem
#pragma unroll
    for (int task = tid; task < 2048; task += 256) {
        int r = task >> 4, c = task & 15;
        int n = n0 + c * 8;
        if (n < N)
            *reinterpret_cast<uint4*>(&g_Db[(size_t)(m0 + r) * N + n]) =
                *reinterpret_cast<const uint4*>(&Ds[r * DSTR + c * 8]);
    }
    if (tid < 128)
        g_tmin[(size_t)(m0 + tid) * NTpad + blockIdx.x] = __uint_as_float(minu[tid]);
}

// ---------------- Dc = sqdist(comb, comb), 32x32 tiles; fused hi16 histogram ----------
#define DCS 36
__global__ void __launch_bounds__(256) k_dc2() {
    __shared__ float AsT[128][DCS];
    __shared__ float BsT[128][DCS];
    int i0 = blockIdx.y * 32, j0 = blockIdx.x * 32;
    int tid = threadIdx.x;
#pragma unroll
    for (int s = tid; s < 1024; s += 256) {
        int k = s & 127, r4 = (s >> 7) * 4;
        float4 va, vb;
        va.x = g_comb[(i0 + r4 + 0) * Dd + k];
        va.y = g_comb[(i0 + r4 + 1) * Dd + k];
        va.z = g_comb[(i0 + r4 + 2) * Dd + k];
        va.w = g_comb[(i0 + r4 + 3) * Dd + k];
        *reinterpret_cast<float4*>(&AsT[k][r4]) = va;
        vb.x = g_comb[(j0 + r4 + 0) * Dd + k];
        vb.y = g_comb[(j0 + r4 + 1) * Dd + k];
        vb.z = g_comb[(j0 + r4 + 2) * Dd + k];
        vb.w = g_comb[(j0 + r4 + 3) * Dd + k];
        *reinterpret_cast<float4*>(&BsT[k][r4]) = vb;
    }
    __syncthreads();
    int tr = tid >> 4, tc = tid & 15;
    float a00 = 0.f, a01 = 0.f, a10 = 0.f, a11 = 0.f;
#pragma unroll 8
    for (int k = 0; k < 128; k++) {
        float2 a = *reinterpret_cast<const float2*>(&AsT[k][tr * 2]);
        float2 b = *reinterpret_cast<const float2*>(&BsT[k][tc * 2]);
        a00 = fmaf(a.x, b.x, a00); a01 = fmaf(a.x, b.y, a01);
        a10 = fmaf(a.y, b.x, a10); a11 = fmaf(a.y, b.y, a11);
    }
    int ri = i0 + tr * 2, rj = j0 + tc * 2;
    float ci0 = g_cn[ri], ci1 = g_cn[ri + 1], cj0 = g_cn[rj], cj1 = g_cn[rj + 1];
    float v00 = fmaxf(ci0 + cj0 - 2.f * a00, 0.f);
    float v01 = fmaxf(ci0 + cj1 - 2.f * a01, 0.f);
    float v10 = fmaxf(ci1 + cj0 - 2.f * a10, 0.f);
    float v11 = fmaxf(ci1 + cj1 - 2.f * a11, 0.f);
    g_Dc[ri * 512 + rj] = v00;       g_Dc[ri * 512 + rj + 1] = v01;
    g_Dc[(ri + 1) * 512 + rj] = v10; g_Dc[(ri + 1) * 512 + rj + 1] = v11;
    atomicAdd(&g_h16[__float_as_uint(v00) >> 16], 1u);
    atomicAdd(&g_h16[__float_as_uint(v01) >> 16], 1u);
    atomicAdd(&g_h16[__float_as_uint(v10) >> 16], 1u);
    atomicAdd(&g_h16[__float_as_uint(v11) >> 16], 1u);
}

// ---------------- decide hi16 buckets for ranks 131072, 131073 ----------------
__global__ void __launch_bounds__(1024) k_decide16() {
    __shared__ unsigned s[1024];
    int t = threadIdx.x;
    unsigned part = 0;
#pragma unroll 8
    for (int i = 0; i < 64; i++) part += g_h16[t * 64 + i];
    s[t] = part;
    __syncthreads();
    for (int off = 1; off < 1024; off <<= 1) {
        unsigned v = (t >= off) ? s[t - off] : 0u;
        __syncthreads();
        s[t] += v;
        __syncthreads();
    }
    unsigned before = (t > 0) ? s[t - 1] : 0u;
    unsigned after = s[t];
#pragma unroll
    for (int which = 0; which < 2; which++) {
        unsigned rank = 131072u + (unsigned)which;
        if (before < rank && rank <= after) {
            unsigned cum = before;
            for (int i = 0; i < 64; i++) {
                unsigned c = g_h16[t * 64 + i];
                if (cum + c >= rank) {
                    if (which == 0) { g_b1 = (unsigned)(t * 64 + i); g_rem1 = rank - cum; }
                    else            { g_b2 = (unsigned)(t * 64 + i); g_rem2 = rank - cum; }
                    break;
                }
                cum += c;
            }
        }
    }
}

// ---------------- lo16 histogram within bucket b1; min lo16 in bucket b2 ----------------
__global__ void k_histlow() {
    unsigned b1 = g_b1, b2 = g_b2;
    unsigned lm = 0xFFFFFFFFu;
    for (int id = blockIdx.x * blockDim.x + threadIdx.x; id < 512 * 512;
         id += gridDim.x * blockDim.x) {
        unsigned u = __float_as_uint(g_Dc[id]);
        unsigned hi = u >> 16;
        if (hi == b1) atomicAdd(&g_h16[65536 + (u & 0xFFFFu)], 1u);
        else if (hi == b2) lm = min(lm, u & 0xFFFFu);
    }
    for (int o = 16; o > 0; o >>= 1) lm = min(lm, __shfl_down_sync(0xffffffffu, lm, o));
    __shared__ unsigned sm[8];
    int w = threadIdx.x >> 5;
    if ((threadIdx.x & 31) == 0) sm[w] = lm;
    __syncthreads();
    if (threadIdx.x == 0) {
        unsigned m = sm[0];
        for (int i = 1; i < 8; i++) m = min(m, sm[i]);
        if (m != 0xFFFFFFFFu) atomicMin(&g_minab, m);
    }
}

// ---------------- decide lo16, compute gamma ----------------
__global__ void __launch_bounds__(1024) k_decidelow() {
    __shared__ unsigned s[1024];
    __shared__ unsigned shv[2];
    int t = threadIdx.x;
    unsigned part = 0;
#pragma unroll 8
    for (int i = 0; i < 64; i++) part += g_h16[65536 + t * 64 + i];
    s[t] = part;
    __syncthreads();
    for (int off = 1; off < 1024; off <<= 1) {
        unsigned v = (t >= off) ? s[t - off] : 0u;
        __syncthreads();
        s[t] += v;
        __syncthreads();
    }
    unsigned before = (t > 0) ? s[t - 1] : 0u;
    unsigned after = s[t];
    unsigned b1 = g_b1, b2 = g_b2;
    bool same = (b1 == b2);
    unsigned ranks[2] = { g_rem1, same ? g_rem2 : 0u };
#pragma unroll
    for (int which = 0; which < 2; which++) {
        if (which == 1 && !same) break;
        unsigned rank = ranks[which];
        if (before < rank && rank <= after) {
            unsigned cum = before;
            for (int i = 0; i < 64; i++) {
                unsigned c = g_h16[65536 + t * 64 + i];
                if (cum + c >= rank) { shv[which] = (unsigned)(t * 64 + i); break; }
                cum += c;
            }
        }
    }
    __syncthreads();
    if (t == 0) {
        unsigned v1 = (b1 << 16) | shv[0];
        unsigned v2 = same ? ((b1 << 16) | shv[1]) : ((b2 << 16) | g_minab);
        float med = 0.5f * (__uint_as_float(v1) + __uint_as_float(v2));
        float sig = med * 0.5f;
        if (sig < 1e-6f) sig = 1.0f;
        g_gval = 1.0f / (sig + EPSf);
    }
}

// ---------------- MMD kernel sums ----------------
__global__ void k_mmd() {
    float g = g_gval;
    float sxx = 0.f, syy = 0.f, sxy = 0.f;
    for (int id = blockIdx.x * blockDim.x + threadIdx.x; id < 512 * 512;
         id += gridDim.x * blockDim.x) {
        int i = id >> 9, j = id & 511;
        float e = expf(-g * g_Dc[id]);
        if (i < Bq) { if (j < Bq) sxx += e; else sxy += e; }
        else if (j >= Bq) syy += e;
    }
    __shared__ float s1[256], s2[256], s3[256];
    int t = threadIdx.x;
    s1[t] = sxx; s2[t] = syy; s3[t] = sxy;
    __syncthreads();
    for (int s = 128; s > 0; s >>= 1) {
        if (t < s) { s1[t] += s1[t + s]; s2[t] += s2[t + s]; s3[t] += s3[t + s]; }
        __syncthreads();
    }
    if (t == 0) {
        atomicAdd(&g_acc[0], s1[0]);
        atomicAdd(&g_acc[1], s2[0]);
        atomicAdd(&g_acc[2], s3[0]);
    }
}

// ---------------- top-50 per row via sorted tile-min guided scan ----------------
__device__ __forceinline__ void bitonic2048(ull* a, int tid) {
    for (int k = 2; k <= 2048; k <<= 1) {
        for (int j = k >> 1; j > 0; j >>= 1) {
#pragma unroll
            for (int u = 0; u < 4; u++) {
                int i = tid + u * 512;
                int ixj = i ^ j;
                if (ixj > i) {
                    bool up = ((i & k) == 0);
                    ull x = a[i], y = a[ixj];
                    if ((x > y) == up) { a[i] = y; a[ixj] = x; }
                }
            }
            __syncthreads();
        }
    }
}

__global__ void __launch_bounds__(512) k_topk(int N) {
    __shared__ ull tiles[2048];
    __shared__ ull cand[2048];
    __shared__ int cnt;
    __shared__ float curT;
    int row = blockIdx.x, tid = threadIdx.x;
    int NT = (N + 127) >> 7;
    for (int t = tid; t < 2048; t += 512)
        tiles[t] = (t < NT)
            ? ((((ull)__float_as_uint(g_tmin[(size_t)row * NTpad + t])) << 32) | (unsigned)t)
            : ~0ull;
    if (tid == 0) { cnt = 0; curT = FLT_MAX; }
    __syncthreads();
    bitonic2048(tiles, tid);                       // ascending by (min,tile)

    const __nv_bfloat16* Drow = g_Db + (size_t)row * N;
    for (int s = 0; s < NT; s += 4) {
        float gmin = __uint_as_float((unsigned)(tiles[s] >> 32));
        if (gmin >= curT) break;
        int slot = tid >> 7, col = tid & 127;
        int s2 = s + slot;
        float T = curT;
        if (s2 < NT) {
            ull key = tiles[s2];
            float tmin = __uint_as_float((unsigned)(key >> 32));
            if (tmin < T) {
                int tl = (int)(key & 0xFFFFFFFFu);
                int n = tl * 128 + col;
                if (n < N) {
                    float v = __bfloat162float(Drow[n]);
                    if (v < T) {
                        int p = atomicAdd(&cnt, 1);
                        cand[p] = (((ull)__float_as_uint(v)) << 32) | (unsigned)n;
                    }
                }
            }
        }
        __syncthreads();
        if (cnt >= 1536) {
            int cs = cnt;
            for (int i = cs + tid; i < 2048; i += 512) cand[i] = ~0ull;
            __syncthreads();
            bitonic2048(cand, tid);
            if (tid == 0) {
                cnt = Kn;
                curT = __uint_as_float((unsigned)(cand[Kn - 1] >> 32));
            }
            __syncthreads();
        }
    }
    int cs = cnt;
    __syncthreads();
    for (int i = cs + tid; i < 2048; i += 512) cand[i] = ~0ull;
    __syncthreads();
    bitonic2048(cand, tid);
    if (tid < Kn) g_post[row * Kn + tid] = (int)(cand[tid] & 0xFFFFFFFFu);
}

// ---------------- union-KL per row (exact fp32) ----------------
__global__ void k_kl(const float* __restrict__ X, const float* __restrict__ pw,
                     const int* __restrict__ pi, const int* __restrict__ qind) {
    int row = blockIdx.x, t = threadIdx.x;
    __shared__ float Tqs[Dd];
    __shared__ int cat[2 * Kn];
    __shared__ float prew[Kn], postw[Kn], l2s[Kn];
    __shared__ float pm[2 * Kn], qm[2 * Kn], mlt[2 * Kn];
    __shared__ float red[Dd];
    __shared__ float Sp, Sq;
    Tqs[t] = g_Tq[row * Dd + t];
    int qi = qind[row];
    if (t < Kn) {
        cat[t] = pi[qi * Kn + t];
        prew[t] = pw[qi * Kn + t];
        cat[Kn + t] = g_post[row * Kn + t];
    }
    __syncthreads();
    int warp = t >> 5, lane = t & 31;
    for (int k = warp; k < Kn; k += 4) {
        const float* xr = X + (size_t)cat[Kn + k] * Dd;
        float s = 0.f;
#pragma unroll
        for (int c = lane; c < Dd; c += 32) {
            float d = Tqs[c] - xr[c];
            s = fmaf(d, d, s);
        }
        for (int o = 16; o > 0; o >>= 1) s += __shfl_down_sync(0xffffffffu, s, o);
        if (lane == 0) l2s[k] = s;
    }
    __syncthreads();
    if (t == 0) {
        float mx = -FLT_MAX;
        for (int k = 0; k < Kn; k++) {
            float z = -l2s[k] * (1.f / TAUf);
            if (z > mx) mx = z;
        }
        float sm = 0.f;
        for (int k = 0; k < Kn; k++) {
            float e = expf(-l2s[k] * (1.f / TAUf) - mx);
            postw[k] = e; sm += e;
        }
        float inv = 1.f / sm;
        for (int k = 0; k < Kn; k++) postw[k] *= inv;
    }
    __syncthreads();
    if (t < 2 * Kn) {
        int id = cat[t];
        int m = 0; float pr = 0.f, qr = 0.f;
        for (int k = 0; k < 2 * Kn; k++) m += (cat[k] == id);
        for (int k = 0; k < Kn; k++) {
            if (cat[k] == id) pr += prew[k];
            if (cat[Kn + k] == id) qr += postw[k];
        }
        pm[t] = fmaxf(pr, EPSf); qm[t] = fmaxf(qr, EPSf); mlt[t] = (float)m;
    }
    __syncthreads();
    if (t == 0) {
        float a = 0.f, bs = 0.f;
        for (int m2 = 0; m2 < 2 * Kn; m2++) { a += pm[m2] / mlt[m2]; bs += qm[m2] / mlt[m2]; }
        Sp = a; Sq = bs;
    }
    __syncthreads();
    float klc = 0.f;
    if (t < 2 * Kn) {
        float p = pm[t] / Sp, q2 = qm[t] / Sq;
        klc = p * (logf(p) - logf(q2)) / mlt[t];
    }
    red[t] = klc;
    __syncthreads();
    for (int s = Dd / 2; s > 0; s >>= 1) {
        if (t < s) red[t] += red[t + s];
        __syncthreads();
    }
    if (t == 0) atomicAdd(&g_acc[4], red[0]);
}

// ---------------- finalize ----------------
__global__ void k_final(const float* __restrict__ W, const float* __restrict__ b,
                        float* __restrict__ out) {
    __shared__ float red[256];
    int t = threadIdx.x;
    float s = 0.f;
    for (int i = t; i < Dd * Dd; i += 256) { float w = W[i]; s = fmaf(w, w, s); }
    if (t < Dd) { float bv = b[t]; s = fmaf(bv, bv, s); }
    red[t] = s;
    __syncthreads();
    for (int st = 128; st > 0; st >>= 1) {
        if (t < st) red[t] += red[t + st];
        __syncthreads();
    }
    if (t == 0) {
        float reg = 0.5f * red[0];
        float inv = 1.0f / 65536.0f;
        float kxx = g_acc[0] * inv, kyy = g_acc[1] * inv, kxy = g_acc[2] * inv;
        float dist = fmaxf(kxx + kyy - 2.f * kxy, 0.f);
        float knn = g_acc[4] / 256.0f;
        float anchor = g_acc[3] / 256.0f;
        float total = dist + knn + 1e-4f * reg + anchor;
        out[0] = total; out[1] = dist; out[2] = knn; out[3] = anchor;
    }
}

// ---------------- launch ----------------
extern "C" void kernel_launch(void* const* d_in, const int* in_sizes, int n_in,
                              void* d_out, int out_size) {
    const float* q  = (const float*)d_in[0];
    const float* X  = (const float*)d_in[1];
    const float* W  = (const float*)d_in[2];
    const float* b  = (const float*)d_in[3];
    const float* pw = (const float*)d_in[4];
    const int* pi   = (const int*)d_in[5];
    const int* qi   = (const int*)d_in[6];
    const int* idx  = (const int*)d_in[7];
    int N = in_sizes[1] / Dd;                       // 200000
    if (N > NxMax) N = NxMax;
    int NT = (N + 127) / 128;

    k_convX<<<(N + 7) / 8, 256>>>(X, N);
    k_tq<<<Bq, Dd>>>(q, W, b);
    k_comb<<<512, Dd>>>(X, idx);
    dim3 gg(NT, Bq / 128);
    k_gemm<<<gg, 256>>>(N);                         // 4th launch -> ncu capture
    dim3 dg(512 / 32, 512 / 32);
    k_dc2<<<dg, 256>>>();
    k_decide16<<<1, 1024>>>();
    k_histlow<<<256, 256>>>();
    k_decidelow<<<1, 1024>>>();
    k_mmd<<<512, 256>>>();
    k_topk<<<Bq, 512>>>(N);
    k_kl<<<Bq, Dd>>>(X, pw, pi, qi);
    k_final<<<1, 256>>>(W, b, (float*)d_out);
}